// round 4
// baseline (speedup 1.0000x reference)
#include <cuda_runtime.h>
#include <math.h>

#define BB 8
#define CC 64
#define HH 128
#define WW 128
#define HW (HH*WW)
#define MX 32
#define MY 17
#define MXY (MX*MY)
#define NPS 10000
#define NPF 5000
#define EDS 64
#define EDF 32
#define NH 4
#define OPH 16

#define MLP_SMEM ((64*128 + 64*64 + 128*64)*4)    /* 81920 B */

// ---------------- scratch (static device globals; no runtime alloc) ----------
__device__ float  g_table[NPS*CC];
__device__ int    g_idx[BB*HW];
__device__ float2 g_lo[BB*CC*MXY];
__device__ double g_magsum[BB];
__device__ int    g_fidx[BB];
__device__ float  g_spat[BB*CC];
__device__ float  g_mhfm[BB*CC];
__device__ float  g_specm[BB*CC];
__device__ float  g_mhf[BB*CC*HW];
__device__ float  g_spec[BB*CC*HW];
__device__ float  g_y[BB*CC*HW];
__device__ double g_ysum[BB];
__device__ double g_ysq[BB];
__device__ float  g_gw[BB*3];
__device__ float  g_mu[BB];
__device__ float  g_rstd[BB];

// ---------------------------------------------------------------------------
__global__ void k_zero() {
    int t = threadIdx.x;
    if (t < BB) { g_magsum[t] = 0.0; g_ysum[t] = 0.0; g_ysq[t] = 0.0; }
}

// table[p][c] = sum_e se_emb[p][e]*se_w[e][c] + se_b[c]
__global__ void k_table(const float* __restrict__ se_emb,
                        const float* __restrict__ se_w,
                        const float* __restrict__ se_b) {
    int t = blockIdx.x*256 + threadIdx.x;
    if (t >= NPS*CC) return;
    int c = t & 63, p = t >> 6;
    float acc = se_b[c];
    const float* er = se_emb + p*EDS;
    #pragma unroll 8
    for (int e = 0; e < EDS; e++) acc += er[e] * se_w[e*CC + c];
    g_table[t] = acc;
}

// spatial hash -> idx[b][pix]
__global__ void k_hash(const float* __restrict__ x) {
    int bx = blockIdx.x;
    int b = bx >> 6, tile = bx & 63;
    int ty = (tile >> 3)*16, tx = (tile & 7)*16;
    int tid = threadIdx.x;
    __shared__ int qs[18*19];
    float acc = 0.f;
    const float* xb = x + (size_t)b*CC*HW;
    int py = tid >> 4, px = tid & 15;
    for (int c = 0; c < CC; c++) {
        const float* xp = xb + c*HW;
        for (int o = tid; o < 324; o += 256) {
            int r = o/18, cl = o%18;
            int gy = min(max(ty + r - 1, 0), HH-1);
            int gx = min(max(tx + cl - 1, 0), WW-1);
            qs[r*19 + cl] = (int)(xp[gy*WW + gx] * 100.0f);
        }
        __syncthreads();
        int hv = 0;
        #pragma unroll
        for (int dy = 0; dy < 3; dy++)
            #pragma unroll
            for (int dx = 0; dx < 3; dx++)
                hv += qs[(py+dy)*19 + px+dx];
        acc += (float)(abs(hv) % NPS);
        __syncthreads();
    }
    g_idx[b*HW + (ty+py)*WW + (tx+px)] = (int)(acc * 0.015625f);
}

// forward low-mode DFT: lo[b,c,kx,ky] = (1/128) sum x e^{-2pi i(kx h + ky w)/128}
__global__ void k_fwd(const float* __restrict__ x) {
    int bc = blockIdx.x; int b = bc >> 6;
    int tid = threadIdx.x;
    __shared__ float2 T[128*MY];     // 17408 B
    __shared__ float2 tw[128];
    __shared__ float  red[256];
    for (int t = tid; t < 128; t += 256) {
        float s, c; sincospif(t * (1.0f/64.0f), &s, &c);
        tw[t] = make_float2(c, s);
    }
    __syncthreads();
    const float* xp = x + (size_t)bc*HW;
    // stage 1: over w (rows read from global; 512B rows stay L1-resident,
    // 17 ky-threads per row broadcast-hit)
    for (int o = tid; o < 128*MY; o += 256) {
        int h = o/17, ky = o%17;
        float cr = 0.f, ci = 0.f;
        const float* row = xp + h*WW;
        for (int w = 0; w < 128; w++) {
            float2 e = tw[(ky*w) & 127];
            float v = __ldg(row + w);
            cr += v*e.x; ci -= v*e.y;
        }
        T[o] = make_float2(cr, ci);
    }
    __syncthreads();
    // stage 2: over h
    float msum = 0.f;
    for (int o = tid; o < MXY; o += 256) {
        int kx = o/17, ky = o%17;
        float cr = 0.f, ci = 0.f;
        for (int h = 0; h < 128; h++) {
            float2 e = tw[(kx*h) & 127];   // e^{-i th} = (c, -s)
            float2 tv = T[h*17 + ky];
            cr += tv.x*e.x + tv.y*e.y;
            ci += tv.y*e.x - tv.x*e.y;
        }
        cr *= 0.0078125f; ci *= 0.0078125f;
        g_lo[bc*MXY + o] = make_float2(cr, ci);
        msum += sqrtf(cr*cr + ci*ci);
    }
    red[tid] = msum; __syncthreads();
    for (int s = 128; s > 0; s >>= 1) { if (tid < s) red[tid] += red[tid+s]; __syncthreads(); }
    if (tid == 0) atomicAdd(&g_magsum[b], (double)red[0]);
}

__global__ void k_fidx() {
    int b = threadIdx.x;
    if (b < BB) {
        float mag = (float)(g_magsum[b] / (double)(CC*MXY));
        g_fidx[b] = ((int)(mag * 1000.0f)) % NPF;
    }
}

__global__ void k_spatmean() {
    int bc = blockIdx.x; int b = bc >> 6, c = bc & 63;
    int tid = threadIdx.x;
    float s = 0.f;
    const int* ip = g_idx + b*HW;
    for (int p = tid; p < HW; p += 256) s += g_table[ip[p]*CC + c];
    __shared__ float red[256];
    red[tid] = s; __syncthreads();
    for (int k = 128; k > 0; k >>= 1) { if (tid < k) red[tid] += red[tid+k]; __syncthreads(); }
    if (tid == 0) g_spat[bc] = red[0] * (1.0f/16384.0f);
}

// per (b,c): frequency filter + spec coefficients, then inverse low-mode DFTs
__global__ void k_coef(const float* __restrict__ wr, const float* __restrict__ wi,
                       const float* __restrict__ mhf_bias,
                       const float* __restrict__ sp_emb,
                       const float* __restrict__ sp_wr, const float* __restrict__ sp_br,
                       const float* __restrict__ sp_wi, const float* __restrict__ sp_bi) {
    int bc = blockIdx.x; int b = bc >> 6, c = bc & 63;
    int hc = c >> 4, oc = c & 15;
    int tid = threadIdx.x;
    __shared__ float Fmr[MXY], Fmi[MXY], Fsr[MXY], Fsi[MXY];
    __shared__ float4 G4[128*MY];
    __shared__ float2 tw[128];
    __shared__ float fes[EDF];
    for (int t = tid; t < 128; t += 256) {
        float s, co; sincospif(t * (1.0f/64.0f), &s, &co);
        tw[t] = make_float2(co, s);
    }
    if (tid < EDF) fes[tid] = sp_emb[g_fidx[b]*EDF + tid];
    __syncthreads();

    const float2* lob = g_lo + b*CC*MXY;
    const float* wrb = wr + (size_t)(hc*CC*OPH + oc)*MXY;
    const float* wib = wi + (size_t)(hc*CC*OPH + oc)*MXY;
    for (int o = tid; o < MXY; o += 256) {
        float mr = 0.f, mi = 0.f;
        for (int i = 0; i < CC; i++) {
            float2 l = lob[i*MXY + o];
            float a = wrb[(size_t)i*OPH*MXY + o];
            float bb = wib[(size_t)i*OPH*MXY + o];
            mr += l.x*a - l.y*bb;
            mi += l.x*bb + l.y*a;
        }
        Fmr[o] = mr; Fmi[o] = mi;
        float sr = sp_br[c*MXY + o], si = sp_bi[c*MXY + o];
        for (int e = 0; e < EDF; e++) {
            float f = fes[e];
            sr += f * sp_wr[(size_t)e*(CC*MXY) + c*MXY + o];
            si += f * sp_wi[(size_t)e*(CC*MXY) + c*MXY + o];
        }
        Fsr[o] = sr; Fsi[o] = si;
        if (o == 0) {
            g_mhfm[bc]  = mr * 0.0078125f + mhf_bias[c];
            g_specm[bc] = sr * 0.0078125f;
        }
    }
    __syncthreads();
    // G[h,ky] = sum_kx F e^{+2pi i kx h/128}
    for (int o = tid; o < 128*MY; o += 256) {
        int h = o/17, ky = o%17;
        float gmr=0,gmi=0,gsr=0,gsi=0;
        for (int kx = 0; kx < MX; kx++) {
            float2 e = tw[(kx*h) & 127];
            int fi = kx*17 + ky;
            float fr = Fmr[fi], f2 = Fmi[fi];
            gmr += fr*e.x - f2*e.y;
            gmi += fr*e.y + f2*e.x;
            fr = Fsr[fi]; f2 = Fsi[fi];
            gsr += fr*e.x - f2*e.y;
            gsi += fr*e.y + f2*e.x;
        }
        G4[o] = make_float4(gmr, gmi, gsr, gsi);
    }
    __syncthreads();
    // stage B: out[h,w] = (1/128)[ReG0 + 2*sum_ky(ReG cos - ImG sin)]
    int w = tid & 127;
    int hbase = (tid >> 7) * 64;
    float cw[17], sw[17];
    cw[0] = 1.f; sw[0] = 0.f;
    #pragma unroll
    for (int ky = 1; ky < 17; ky++) {
        float2 e = tw[(ky*w) & 127];
        cw[ky] =  2.f*e.x;
        sw[ky] = -2.f*e.y;
    }
    float bias = mhf_bias[c];
    float* mout = g_mhf  + (size_t)bc*HW;
    float* sout = g_spec + (size_t)bc*HW;
    for (int h = hbase; h < hbase + 64; h++) {
        const float4* Gr = G4 + h*17;
        float vm = 0.f, vs = 0.f;
        #pragma unroll
        for (int ky = 0; ky < 17; ky++) {
            float4 g = Gr[ky];
            vm += g.x*cw[ky] + g.y*sw[ky];
            vs += g.z*cw[ky] + g.w*sw[ky];
        }
        mout[h*WW + w] = vm * 0.0078125f + bias;
        sout[h*WW + w] = vs * 0.0078125f;
    }
}

__global__ void k_gate(const float* __restrict__ gw1, const float* __restrict__ gb1,
                       const float* __restrict__ gw2, const float* __restrict__ gb2) {
    __shared__ float gi[BB*192];
    __shared__ float h1[BB*64];
    int tid = threadIdx.x;
    for (int o = tid; o < BB*192; o += 512) {
        int b = o/192, k = o%192;
        float v;
        if (k < 64)       v = g_spat[b*64 + k];
        else if (k < 128) v = g_mhfm[b*64 + k - 64];
        else              v = g_specm[b*64 + k - 128];
        gi[o] = v;
    }
    __syncthreads();
    {
        int b = tid >> 6, j = tid & 63;
        float a = gb1[j];
        for (int k = 0; k < 192; k++) a += gi[b*192 + k] * gw1[k*64 + j];
        h1[tid] = 0.5f*a*(1.0f + erff(a*0.70710678118654752f));
    }
    __syncthreads();
    if (tid < BB) {
        int b = tid;
        float l[3];
        #pragma unroll
        for (int m = 0; m < 3; m++) {
            float a = gb2[m];
            for (int j = 0; j < 64; j++) a += h1[b*64 + j] * gw2[j*3 + m];
            l[m] = a;
        }
        float mx = fmaxf(l[0], fmaxf(l[1], l[2]));
        float e0 = expf(l[0]-mx), e1 = expf(l[1]-mx), e2 = expf(l[2]-mx);
        float inv = 1.0f/(e0+e1+e2);
        g_gw[b*3+0] = e0*inv; g_gw[b*3+1] = e1*inv; g_gw[b*3+2] = e2*inv;
    }
}

// y = gate-weighted fuse + skip conv + skip_b; accumulate LN stats
__global__ void k_y(const float* __restrict__ x,
                    const float* __restrict__ skip_w,
                    const float* __restrict__ skip_b) {
    int bx = blockIdx.x;
    int b = bx >> 8, tile = bx & 255;
    int pbase = tile * 64;
    int tid = threadIdx.x;
    __shared__ float buf[64*65];   // xs (i*64+p) then spatial gather (p*65+c)
    __shared__ float ys[64*64];    // skip result [c*64+p]
    __shared__ int idxs[64];
    __shared__ float red[256], redq[256];

    if (tid < 64) idxs[tid] = g_idx[b*HW + pbase + tid];
    for (int o = tid; o < 4096; o += 256) {
        int i = o >> 6, p = o & 63;
        buf[i*64 + p] = x[((size_t)(b*64 + i))*HW + pbase + p];
    }
    __syncthreads();
    // skip 1x1 conv
    {
        int p = tid & 63, g = tid >> 6; int c0 = g*16;
        float acc[16];
        #pragma unroll
        for (int q = 0; q < 16; q++) acc[q] = 0.f;
        for (int i = 0; i < 64; i++) {
            float xv = buf[i*64 + p];
            const float4* swr = (const float4*)(skip_w + i*64 + c0);
            float4 a0 = swr[0], a1 = swr[1], a2 = swr[2], a3 = swr[3];
            acc[0] += xv*a0.x; acc[1] += xv*a0.y; acc[2] += xv*a0.z; acc[3] += xv*a0.w;
            acc[4] += xv*a1.x; acc[5] += xv*a1.y; acc[6] += xv*a1.z; acc[7] += xv*a1.w;
            acc[8] += xv*a2.x; acc[9] += xv*a2.y; acc[10]+= xv*a2.z; acc[11]+= xv*a2.w;
            acc[12]+= xv*a3.x; acc[13]+= xv*a3.y; acc[14]+= xv*a3.z; acc[15]+= xv*a3.w;
        }
        #pragma unroll
        for (int q = 0; q < 16; q++) ys[(c0+q)*64 + p] = acc[q];
    }
    __syncthreads();
    // spatial gather (coalesced), into padded buf[p*65+c]
    for (int o = tid; o < 4096; o += 256) {
        int p = o >> 6, cc2 = o & 63;
        buf[p*65 + cc2] = g_table[idxs[p]*CC + cc2];
    }
    __syncthreads();
    float ga = g_gw[b*3], gbt = g_gw[b*3+1], gm = g_gw[b*3+2];
    float lsum = 0.f, lsq = 0.f;
    for (int o = tid; o < 4096; o += 256) {
        int c = o >> 6, p = o & 63;
        size_t gidx = ((size_t)(b*64 + c))*HW + pbase + p;
        float yv = ga*buf[p*65 + c] + gbt*g_mhf[gidx] + gm*g_spec[gidx]
                 + ys[c*64 + p] + skip_b[c];
        g_y[gidx] = yv;
        lsum += yv; lsq += yv*yv;
    }
    red[tid] = lsum; redq[tid] = lsq; __syncthreads();
    for (int s = 128; s > 0; s >>= 1) {
        if (tid < s) { red[tid] += red[tid+s]; redq[tid] += redq[tid+s]; }
        __syncthreads();
    }
    if (tid == 0) {
        atomicAdd(&g_ysum[b], (double)red[0]);
        atomicAdd(&g_ysq[b],  (double)redq[0]);
    }
}

__global__ void k_stats() {
    int b = threadIdx.x;
    if (b < BB) {
        double n = (double)(CC*HW);
        double mu = g_ysum[b] / n;
        double var = g_ysq[b] / n - mu*mu;
        g_mu[b] = (float)mu;
        g_rstd[b] = (float)(1.0 / sqrt(var + 1e-5));
    }
}

// layernorm + MLP + residual
__global__ void k_mlp(const float* __restrict__ norm_g, const float* __restrict__ norm_b,
                      const float* __restrict__ w1, const float* __restrict__ b1,
                      const float* __restrict__ w2, const float* __restrict__ b2,
                      float* __restrict__ out) {
    extern __shared__ float sm[];
    float* w12 = sm;            // 8192: w1 then reused for w2
    float* yns = sm + 8192;     // 4096: yn [c*64+p], later MLP out
    float* hs  = sm + 8192 + 4096; // 8192: hidden [j*64+p]
    int bx = blockIdx.x;
    int b = bx >> 8, tile = bx & 255;
    int pbase = tile * 64;
    int tid = threadIdx.x;

    for (int o = tid; o < 8192; o += 256) w12[o] = w1[o];
    float mu = g_mu[b], rstd = g_rstd[b];
    for (int o = tid; o < 4096; o += 256) {
        int c = o >> 6, p = o & 63;
        float yv = g_y[((size_t)(b*64 + c))*HW + pbase + p];
        yns[c*64 + p] = (yv - mu)*rstd*norm_g[c] + norm_b[c];
    }
    __syncthreads();
    // hidden: h[j][p], j<128
    {
        int p = tid & 63, jg = tid >> 6;
        float acc[32];
        #pragma unroll
        for (int q = 0; q < 32; q++) acc[q] = 0.f;
        const float4* w14 = (const float4*)w12;
        for (int c = 0; c < 64; c++) {
            float yv = yns[c*64 + p];
            const float4* row = w14 + c*32 + jg*8;
            #pragma unroll
            for (int q = 0; q < 8; q++) {
                float4 wv = row[q];
                acc[q*4+0] += yv*wv.x; acc[q*4+1] += yv*wv.y;
                acc[q*4+2] += yv*wv.z; acc[q*4+3] += yv*wv.w;
            }
        }
        #pragma unroll
        for (int q = 0; q < 32; q++) {
            int j = jg*32 + q;
            float v = acc[q] + b1[j];
            hs[j*64 + p] = 0.5f*v*(1.0f + erff(v*0.70710678118654752f));
        }
    }
    __syncthreads();
    for (int o = tid; o < 8192; o += 256) w12[o] = w2[o];
    __syncthreads();
    // out: os[c][p]
    {
        int p = tid & 63, cg = tid >> 6;
        float acc2[16];
        #pragma unroll
        for (int q = 0; q < 16; q++) acc2[q] = 0.f;
        const float4* w24 = (const float4*)w12;
        for (int j = 0; j < 128; j++) {
            float hv = hs[j*64 + p];
            const float4* row = w24 + j*16 + cg*4;
            #pragma unroll
            for (int q = 0; q < 4; q++) {
                float4 wv = row[q];
                acc2[q*4+0] += hv*wv.x; acc2[q*4+1] += hv*wv.y;
                acc2[q*4+2] += hv*wv.z; acc2[q*4+3] += hv*wv.w;
            }
        }
        __syncthreads();
        #pragma unroll
        for (int q = 0; q < 16; q++) yns[(cg*16 + q)*64 + p] = acc2[q];
    }
    __syncthreads();
    for (int o = tid; o < 4096; o += 256) {
        int c = o >> 6, p = o & 63;
        size_t gi2 = ((size_t)(b*64 + c))*HW + pbase + p;
        out[gi2] = g_y[gi2] + yns[c*64 + p] + b2[c];
    }
}

// ---------------------------------------------------------------------------
extern "C" void kernel_launch(void* const* d_in, const int* in_sizes, int n_in,
                              void* d_out, int out_size) {
    const float* x        = (const float*)d_in[0];
    const float* se_emb   = (const float*)d_in[1];
    const float* se_w     = (const float*)d_in[2];
    const float* se_b     = (const float*)d_in[3];
    const float* mhf_wr   = (const float*)d_in[4];
    const float* mhf_wi   = (const float*)d_in[5];
    const float* mhf_bias = (const float*)d_in[6];
    const float* sp_emb   = (const float*)d_in[7];
    const float* sp_wr    = (const float*)d_in[8];
    const float* sp_br    = (const float*)d_in[9];
    const float* sp_wi    = (const float*)d_in[10];
    const float* sp_bi    = (const float*)d_in[11];
    const float* gate_w1  = (const float*)d_in[12];
    const float* gate_b1  = (const float*)d_in[13];
    const float* gate_w2  = (const float*)d_in[14];
    const float* gate_b2  = (const float*)d_in[15];
    const float* skip_w   = (const float*)d_in[16];
    const float* skip_b   = (const float*)d_in[17];
    const float* norm_g   = (const float*)d_in[18];
    const float* norm_b   = (const float*)d_in[19];
    const float* mlp_w1   = (const float*)d_in[20];
    const float* mlp_b1   = (const float*)d_in[21];
    const float* mlp_w2   = (const float*)d_in[22];
    const float* mlp_b2   = (const float*)d_in[23];
    float* out = (float*)d_out;

    cudaFuncSetAttribute(k_mlp, cudaFuncAttributeMaxDynamicSharedMemorySize, MLP_SMEM);

    k_zero<<<1, 32>>>();
    k_table<<<(NPS*CC + 255)/256, 256>>>(se_emb, se_w, se_b);
    k_hash<<<BB*64, 256>>>(x);
    k_fwd<<<BB*CC, 256>>>(x);
    k_fidx<<<1, 32>>>();
    k_spatmean<<<BB*CC, 256>>>();
    k_coef<<<BB*CC, 256>>>(mhf_wr, mhf_wi, mhf_bias, sp_emb, sp_wr, sp_br, sp_wi, sp_bi);
    k_gate<<<1, 512>>>(gate_w1, gate_b1, gate_w2, gate_b2);
    k_y<<<BB*256, 256>>>(x, skip_w, skip_b);
    k_stats<<<1, 32>>>();
    k_mlp<<<BB*256, 256, MLP_SMEM>>>(norm_g, norm_b, mlp_w1, mlp_b1, mlp_w2, mlp_b2, out);
}

// round 5
// speedup vs baseline: 1.0360x; 1.0360x over previous
#include <cuda_runtime.h>
#include <math.h>

#define BB 8
#define CC 64
#define HH 128
#define WW 128
#define HW (HH*WW)
#define MX 32
#define MY 17
#define MXY (MX*MY)
#define NPS 10000
#define NPF 5000
#define EDS 64
#define EDF 32
#define NH 4
#define OPH 16

#define MLP_SMEM ((64*128 + 64*64 + 128*64)*4)    /* 81920 B */
#define FWD_SMEM (32768 + 17408 + 1024 + 1024 + 2048)  /* 54272 B */

typedef unsigned long long ull;
__device__ __forceinline__ ull pk(float x, float y){
    ull r; asm("mov.b64 %0, {%1,%2};" : "=l"(r) : "f"(x), "f"(y)); return r;
}
__device__ __forceinline__ void upk(ull v, float& x, float& y){
    asm("mov.b64 {%0,%1}, %2;" : "=f"(x), "=f"(y) : "l"(v));
}
__device__ __forceinline__ ull ffma2(ull a, ull b, ull c){
    ull d; asm("fma.rn.f32x2 %0, %1, %2, %3;" : "=l"(d) : "l"(a), "l"(b), "l"(c)); return d;
}

// ---------------- scratch (static device globals; no runtime alloc) ----------
__device__ float  g_table[NPS*CC];
__device__ int    g_idx[BB*HW];
__device__ int    g_hist[BB*NPS];
__device__ float2 g_lo[BB*CC*MXY];
__device__ double g_magsum[BB];
__device__ int    g_fidx[BB];
__device__ float  g_spat[BB*CC];
__device__ float  g_mhfm[BB*CC];
__device__ float  g_specm[BB*CC];
__device__ float  g_mhf[BB*CC*HW];
__device__ float  g_spec[BB*CC*HW];
__device__ float  g_y[BB*CC*HW];
__device__ double g_ysum[BB];
__device__ double g_ysq[BB];
__device__ float  g_gw[BB*3];
__device__ float  g_mu[BB];
__device__ float  g_rstd[BB];

// ---------------------------------------------------------------------------
__global__ void k_zero() {
    int t = blockIdx.x*256 + threadIdx.x;
    if (t < BB*NPS) g_hist[t] = 0;
    if (t < BB) { g_magsum[t] = 0.0; g_ysum[t] = 0.0; g_ysq[t] = 0.0; }
}

// table[p][c] = sum_e se_emb[p][e]*se_w[e][c] + se_b[c]
__global__ void k_table(const float* __restrict__ se_emb,
                        const float* __restrict__ se_w,
                        const float* __restrict__ se_b) {
    int t = blockIdx.x*256 + threadIdx.x;
    if (t >= NPS*CC) return;
    int c = t & 63, p = t >> 6;
    float acc = se_b[c];
    const float* er = se_emb + p*EDS;
    #pragma unroll 8
    for (int e = 0; e < EDS; e++) acc += er[e] * se_w[e*CC + c];
    g_table[t] = acc;
}

// spatial hash -> idx[b][pix], plus histogram. Separable box filter, one
// block per (b, h), 128 threads = one pixel each.
__global__ void k_hash(const float* __restrict__ x) {
    int bid = blockIdx.x;
    int b = bid >> 7, h = bid & 127;
    int w = threadIdx.x;
    int hm = max(h-1, 0), hp = min(h+1, HH-1);
    int wm = max(w-1, 0), wp = min(w+1, WW-1);
    __shared__ int sv[2][128];
    const float* xb = x + (size_t)b*CC*HW;
    float acc = 0.f;
    for (int c = 0; c < CC; c++) {
        const float* xc = xb + c*HW;
        int V = (int)(xc[hm*WW + w]*100.0f)
              + (int)(xc[h *WW + w]*100.0f)
              + (int)(xc[hp*WW + w]*100.0f);
        int* buf = sv[c & 1];
        buf[w] = V;
        __syncthreads();
        int hv = buf[wm] + buf[w] + buf[wp];
        acc += (float)(abs(hv) % NPS);
    }
    int idx = (int)(acc * 0.015625f);
    g_idx[b*HW + h*WW + w] = idx;
    atomicAdd(&g_hist[b*NPS + idx], 1);
}

// spatial mean via histogram: spat[b][c] = sum_n hist[b][n]*table[n][c] / 16384
__global__ void k_spat() {
    int b = blockIdx.x;
    int tid = threadIdx.x;
    int c = tid & 63, rep = tid >> 6;
    float acc = 0.f;
    const int* hb = g_hist + b*NPS;
    for (int n = rep; n < NPS; n += 4)
        acc += (float)hb[n] * g_table[n*CC + c];
    __shared__ float red[256];
    red[tid] = acc; __syncthreads();
    if (tid < 64)
        g_spat[b*CC + c] = (red[tid] + red[tid+64] + red[tid+128] + red[tid+192])
                           * (1.0f/16384.0f);
}

// forward low-mode DFT: lo[b,c,kx,ky] = (1/128) sum x e^{-2pi i(kx h + ky w)/128}
// smem-staged, register-blocked, f32x2 FMAs.
__global__ void k_fwd(const float* __restrict__ x) {
    extern __shared__ float sm[];
    float*  xs  = sm;                        // 64*128 rotated tile chunk
    float2* T   = (float2*)(sm + 8192);      // 128*17
    float2* twp = T + 2176;                  // {cos, sin}
    float2* twm = twp + 128;                 // {cos, -sin}
    double* red = (double*)(twm + 128);      // 256

    int bc = blockIdx.x, b = bc >> 6;
    int tid = threadIdx.x;
    for (int t = tid; t < 128; t += 256) {
        float s, c; sincospif(t * (1.0f/64.0f), &s, &c);
        twp[t] = make_float2(c, s);
        twm[t] = make_float2(c, -s);
    }
    __syncthreads();
    const float* xp = x + (size_t)bc*HW;
    int r = tid & 63, q = tid >> 6;
    int k0 = (q == 0) ? 0 : (4*q + 1);       // ky groups: {0..4},{5..8},{9..12},{13..16}

    for (int chunk = 0; chunk < 2; chunk++) {
        for (int o = tid; o < 8192; o += 256) {
            int rr = o >> 7, w = o & 127;
            xs[rr*128 + ((w + rr) & 127)] = xp[(size_t)(chunk*64 + rr)*WW + w];
        }
        __syncthreads();
        ull a0 = 0, a1 = 0, a2 = 0, a3 = 0, a4 = 0;
        for (int w = 0; w < 128; w++) {
            float v = xs[r*128 + ((w + r) & 127)];
            ull v2 = pk(v, v);
            float2 e;
            e = twm[( k0   *w) & 127]; a0 = ffma2(v2, pk(e.x, e.y), a0);
            e = twm[((k0+1)*w) & 127]; a1 = ffma2(v2, pk(e.x, e.y), a1);
            e = twm[((k0+2)*w) & 127]; a2 = ffma2(v2, pk(e.x, e.y), a2);
            e = twm[((k0+3)*w) & 127]; a3 = ffma2(v2, pk(e.x, e.y), a3);
            if (q == 0) { e = twm[(4*w) & 127]; a4 = ffma2(v2, pk(e.x, e.y), a4); }
        }
        int h = chunk*64 + r;
        float cr, ci;
        upk(a0, cr, ci); T[h*17 + k0    ] = make_float2(cr, ci);
        upk(a1, cr, ci); T[h*17 + k0 + 1] = make_float2(cr, ci);
        upk(a2, cr, ci); T[h*17 + k0 + 2] = make_float2(cr, ci);
        upk(a3, cr, ci); T[h*17 + k0 + 3] = make_float2(cr, ci);
        if (q == 0) { upk(a4, cr, ci); T[h*17 + 4] = make_float2(cr, ci); }
        __syncthreads();
    }

    // stage 2 over h: 136 threads x 4 kx
    float msum = 0.f;
    if (tid < 136) {
        int kxg = tid / 17, ky = tid % 17;
        float cr[4] = {0,0,0,0}, ci[4] = {0,0,0,0};
        for (int h = 0; h < 128; h++) {
            float2 tv = T[h*17 + ky];
            #pragma unroll
            for (int u = 0; u < 4; u++) {
                float2 e = twp[((kxg*4 + u)*h) & 127];
                cr[u] += tv.x*e.x + tv.y*e.y;
                ci[u] += tv.y*e.x - tv.x*e.y;
            }
        }
        #pragma unroll
        for (int u = 0; u < 4; u++) {
            float a = cr[u]*0.0078125f, bb = ci[u]*0.0078125f;
            g_lo[bc*MXY + (kxg*4 + u)*17 + ky] = make_float2(a, bb);
            msum += sqrtf(a*a + bb*bb);
        }
    }
    red[tid] = (double)msum; __syncthreads();
    for (int s = 128; s > 0; s >>= 1) {
        if (tid < s) red[tid] += red[tid+s];
        __syncthreads();
    }
    if (tid == 0) atomicAdd(&g_magsum[b], red[0]);
}

__global__ void k_fidx() {
    int b = threadIdx.x;
    if (b < BB) {
        float mag = (float)(g_magsum[b] / (double)(CC*MXY));
        g_fidx[b] = ((int)(mag * 1000.0f)) % NPF;
    }
}

// per (b,c): frequency filter + spec coefficients, then inverse low-mode DFTs
__global__ void k_coef(const float* __restrict__ wr, const float* __restrict__ wi,
                       const float* __restrict__ mhf_bias,
                       const float* __restrict__ sp_emb,
                       const float* __restrict__ sp_wr, const float* __restrict__ sp_br,
                       const float* __restrict__ sp_wi, const float* __restrict__ sp_bi) {
    int bc = blockIdx.x; int b = bc >> 6, c = bc & 63;
    int hc = c >> 4, oc = c & 15;
    int tid = threadIdx.x;
    __shared__ float2 Fm[MXY], Fs[MXY];
    __shared__ float2 Gm[128*MY], Gs[128*MY];
    __shared__ float2 twp[128], twn[128];
    __shared__ float fes[EDF];
    for (int t = tid; t < 128; t += 256) {
        float s, co; sincospif(t * (1.0f/64.0f), &s, &co);
        twp[t] = make_float2(co, s);
        twn[t] = make_float2(-s, co);
    }
    if (tid < EDF) fes[tid] = sp_emb[g_fidx[b]*EDF + tid];
    __syncthreads();

    const float2* lob = g_lo + b*CC*MXY;
    const float* wrb = wr + (size_t)(hc*CC*OPH + oc)*MXY;
    const float* wib = wi + (size_t)(hc*CC*OPH + oc)*MXY;
    for (int o = tid; o < MXY; o += 256) {
        float mr = 0.f, mi = 0.f;
        for (int i = 0; i < CC; i++) {
            float2 l = lob[i*MXY + o];
            float a = wrb[(size_t)i*OPH*MXY + o];
            float bb = wib[(size_t)i*OPH*MXY + o];
            mr += l.x*a - l.y*bb;
            mi += l.x*bb + l.y*a;
        }
        Fm[o] = make_float2(mr, mi);
        float sr = sp_br[c*MXY + o], si = sp_bi[c*MXY + o];
        for (int e = 0; e < EDF; e++) {
            float f = fes[e];
            sr += f * sp_wr[(size_t)e*(CC*MXY) + c*MXY + o];
            si += f * sp_wi[(size_t)e*(CC*MXY) + c*MXY + o];
        }
        Fs[o] = make_float2(sr, si);
        if (o == 0) {
            g_mhfm[bc]  = mr * 0.0078125f + mhf_bias[c];
            g_specm[bc] = sr * 0.0078125f;
        }
    }
    __syncthreads();
    // G[h,ky] = sum_kx F e^{+2pi i kx h/128}  (packed complex FMA)
    for (int o = tid; o < 128*MY; o += 256) {
        int h = o/17, ky = o%17;
        ull gm = 0, gs = 0;
        for (int kx = 0; kx < MX; kx++) {
            int ti = (kx*h) & 127;
            float2 ep2 = twp[ti], en2 = twn[ti];
            ull ep = pk(ep2.x, ep2.y), en = pk(en2.x, en2.y);
            float2 fm = Fm[kx*17 + ky], fs = Fs[kx*17 + ky];
            gm = ffma2(pk(fm.x, fm.x), ep, gm);
            gm = ffma2(pk(fm.y, fm.y), en, gm);
            gs = ffma2(pk(fs.x, fs.x), ep, gs);
            gs = ffma2(pk(fs.y, fs.y), en, gs);
        }
        float a, bb;
        upk(gm, a, bb); Gm[o] = make_float2(a, bb);
        upk(gs, a, bb); Gs[o] = make_float2(a, bb);
    }
    __syncthreads();
    // stage B: out[h,w] = (1/128)[ReG0 + 2*sum_ky(ReG cos - ImG sin)]
    int w = tid & 127;
    int hbase = (tid >> 7) * 64;
    ull cs[17];
    cs[0] = pk(1.f, 0.f);
    #pragma unroll
    for (int ky = 1; ky < 17; ky++) {
        float2 e = twp[(ky*w) & 127];
        cs[ky] = pk(2.f*e.x, -2.f*e.y);
    }
    float bias = mhf_bias[c];
    float* mout = g_mhf  + (size_t)bc*HW;
    float* sout = g_spec + (size_t)bc*HW;
    for (int h = hbase; h < hbase + 64; h++) {
        const float2* Gmr = Gm + h*17;
        const float2* Gsr = Gs + h*17;
        ull am = 0, as = 0;
        #pragma unroll
        for (int ky = 0; ky < 17; ky++) {
            float2 gmv = Gmr[ky], gsv = Gsr[ky];
            am = ffma2(pk(gmv.x, gmv.y), cs[ky], am);
            as = ffma2(pk(gsv.x, gsv.y), cs[ky], as);
        }
        float m0, m1, s0, s1;
        upk(am, m0, m1); upk(as, s0, s1);
        mout[h*WW + w] = (m0 + m1) * 0.0078125f + bias;
        sout[h*WW + w] = (s0 + s1) * 0.0078125f;
    }
}

__global__ void k_gate(const float* __restrict__ gw1, const float* __restrict__ gb1,
                       const float* __restrict__ gw2, const float* __restrict__ gb2) {
    __shared__ float gi[BB*192];
    __shared__ float h1[BB*64];
    int tid = threadIdx.x;
    for (int o = tid; o < BB*192; o += 512) {
        int b = o/192, k = o%192;
        float v;
        if (k < 64)       v = g_spat[b*64 + k];
        else if (k < 128) v = g_mhfm[b*64 + k - 64];
        else              v = g_specm[b*64 + k - 128];
        gi[o] = v;
    }
    __syncthreads();
    {
        int b = tid >> 6, j = tid & 63;
        float a = gb1[j];
        for (int k = 0; k < 192; k++) a += gi[b*192 + k] * gw1[k*64 + j];
        h1[tid] = 0.5f*a*(1.0f + erff(a*0.70710678118654752f));
    }
    __syncthreads();
    if (tid < BB) {
        int b = tid;
        float l[3];
        #pragma unroll
        for (int m = 0; m < 3; m++) {
            float a = gb2[m];
            for (int j = 0; j < 64; j++) a += h1[b*64 + j] * gw2[j*3 + m];
            l[m] = a;
        }
        float mx = fmaxf(l[0], fmaxf(l[1], l[2]));
        float e0 = expf(l[0]-mx), e1 = expf(l[1]-mx), e2 = expf(l[2]-mx);
        float inv = 1.0f/(e0+e1+e2);
        g_gw[b*3+0] = e0*inv; g_gw[b*3+1] = e1*inv; g_gw[b*3+2] = e2*inv;
    }
}

// y = gate-weighted fuse + skip conv + skip_b; accumulate LN stats
__global__ void k_y(const float* __restrict__ x,
                    const float* __restrict__ skip_w,
                    const float* __restrict__ skip_b) {
    int bx = blockIdx.x;
    int b = bx >> 8, tile = bx & 255;
    int pbase = tile * 64;
    int tid = threadIdx.x;
    __shared__ float buf[64*65];   // xs (i*64+p) then spatial gather (p*65+c)
    __shared__ float ys[64*64];    // skip result [c*64+p]
    __shared__ int idxs[64];
    __shared__ float red[256], redq[256];

    if (tid < 64) idxs[tid] = g_idx[b*HW + pbase + tid];
    for (int o = tid; o < 4096; o += 256) {
        int i = o >> 6, p = o & 63;
        buf[i*64 + p] = x[((size_t)(b*64 + i))*HW + pbase + p];
    }
    __syncthreads();
    // skip 1x1 conv (packed f32x2)
    {
        int p = tid & 63, g = tid >> 6; int c0 = g*16;
        ull acc[8];
        #pragma unroll
        for (int t = 0; t < 8; t++) acc[t] = 0;
        for (int i = 0; i < 64; i++) {
            float xv = buf[i*64 + p];
            ull xv2 = pk(xv, xv);
            const float4* swr = (const float4*)(skip_w + i*64 + c0);
            #pragma unroll
            for (int t = 0; t < 4; t++) {
                float4 wv = swr[t];
                acc[t*2]   = ffma2(xv2, pk(wv.x, wv.y), acc[t*2]);
                acc[t*2+1] = ffma2(xv2, pk(wv.z, wv.w), acc[t*2+1]);
            }
        }
        #pragma unroll
        for (int t = 0; t < 8; t++) {
            float v0, v1; upk(acc[t], v0, v1);
            ys[(c0 + 2*t    )*64 + p] = v0;
            ys[(c0 + 2*t + 1)*64 + p] = v1;
        }
    }
    __syncthreads();
    // spatial gather (coalesced), into padded buf[p*65+c]
    for (int o = tid; o < 4096; o += 256) {
        int p = o >> 6, cc2 = o & 63;
        buf[p*65 + cc2] = g_table[idxs[p]*CC + cc2];
    }
    __syncthreads();
    float ga = g_gw[b*3], gbt = g_gw[b*3+1], gm = g_gw[b*3+2];
    float lsum = 0.f, lsq = 0.f;
    for (int o = tid; o < 4096; o += 256) {
        int c = o >> 6, p = o & 63;
        size_t gidx = ((size_t)(b*64 + c))*HW + pbase + p;
        float yv = ga*buf[p*65 + c] + gbt*g_mhf[gidx] + gm*g_spec[gidx]
                 + ys[c*64 + p] + skip_b[c];
        g_y[gidx] = yv;
        lsum += yv; lsq += yv*yv;
    }
    red[tid] = lsum; redq[tid] = lsq; __syncthreads();
    for (int s = 128; s > 0; s >>= 1) {
        if (tid < s) { red[tid] += red[tid+s]; redq[tid] += redq[tid+s]; }
        __syncthreads();
    }
    if (tid == 0) {
        atomicAdd(&g_ysum[b], (double)red[0]);
        atomicAdd(&g_ysq[b],  (double)redq[0]);
    }
}

__global__ void k_stats() {
    int b = threadIdx.x;
    if (b < BB) {
        double n = (double)(CC*HW);
        double mu = g_ysum[b] / n;
        double var = g_ysq[b] / n - mu*mu;
        g_mu[b] = (float)mu;
        g_rstd[b] = (float)(1.0 / sqrt(var + 1e-5));
    }
}

// layernorm + MLP + residual (packed f32x2 GEMMs)
__global__ void k_mlp(const float* __restrict__ norm_g, const float* __restrict__ norm_b,
                      const float* __restrict__ w1, const float* __restrict__ b1,
                      const float* __restrict__ w2, const float* __restrict__ b2,
                      float* __restrict__ out) {
    extern __shared__ float sm[];
    float* w12 = sm;               // 8192: w1 then reused for w2
    float* yns = sm + 8192;        // 4096: yn [c*64+p], later MLP out
    float* hs  = sm + 8192 + 4096; // 8192: hidden [j*64+p]
    int bx = blockIdx.x;
    int b = bx >> 8, tile = bx & 255;
    int pbase = tile * 64;
    int tid = threadIdx.x;

    for (int o = tid; o < 8192; o += 256) w12[o] = w1[o];
    float mu = g_mu[b], rstd = g_rstd[b];
    for (int o = tid; o < 4096; o += 256) {
        int c = o >> 6, p = o & 63;
        float yv = g_y[((size_t)(b*64 + c))*HW + pbase + p];
        yns[c*64 + p] = (yv - mu)*rstd*norm_g[c] + norm_b[c];
    }
    __syncthreads();
    // hidden: h[j][p], j<128
    {
        int p = tid & 63, jg = tid >> 6;
        ull acc[16];
        #pragma unroll
        for (int t = 0; t < 16; t++) acc[t] = 0;
        const float4* w14 = (const float4*)w12;
        for (int c = 0; c < 64; c++) {
            float yv = yns[c*64 + p];
            ull yv2 = pk(yv, yv);
            const float4* row = w14 + c*32 + jg*8;
            #pragma unroll
            for (int t = 0; t < 8; t++) {
                float4 wv = row[t];
                acc[t*2]   = ffma2(yv2, pk(wv.x, wv.y), acc[t*2]);
                acc[t*2+1] = ffma2(yv2, pk(wv.z, wv.w), acc[t*2+1]);
            }
        }
        #pragma unroll
        for (int t = 0; t < 16; t++) {
            float v0, v1; upk(acc[t], v0, v1);
            int j = jg*32 + 2*t;
            float a0 = v0 + b1[j], a1 = v1 + b1[j+1];
            hs[j*64 + p]     = 0.5f*a0*(1.0f + erff(a0*0.70710678118654752f));
            hs[(j+1)*64 + p] = 0.5f*a1*(1.0f + erff(a1*0.70710678118654752f));
        }
    }
    __syncthreads();
    for (int o = tid; o < 8192; o += 256) w12[o] = w2[o];
    __syncthreads();
    // out: os[c][p]
    {
        int p = tid & 63, cg = tid >> 6;
        ull acc2[8];
        #pragma unroll
        for (int t = 0; t < 8; t++) acc2[t] = 0;
        const float4* w24 = (const float4*)w12;
        for (int j = 0; j < 128; j++) {
            float hv = hs[j*64 + p];
            ull hv2 = pk(hv, hv);
            const float4* row = w24 + j*16 + cg*4;
            #pragma unroll
            for (int t = 0; t < 4; t++) {
                float4 wv = row[t];
                acc2[t*2]   = ffma2(hv2, pk(wv.x, wv.y), acc2[t*2]);
                acc2[t*2+1] = ffma2(hv2, pk(wv.z, wv.w), acc2[t*2+1]);
            }
        }
        __syncthreads();   // all reads of yns done
        #pragma unroll
        for (int t = 0; t < 8; t++) {
            float v0, v1; upk(acc2[t], v0, v1);
            yns[(cg*16 + 2*t    )*64 + p] = v0;
            yns[(cg*16 + 2*t + 1)*64 + p] = v1;
        }
    }
    __syncthreads();
    for (int o = tid; o < 4096; o += 256) {
        int c = o >> 6, p = o & 63;
        size_t gi2 = ((size_t)(b*64 + c))*HW + pbase + p;
        out[gi2] = g_y[gi2] + yns[c*64 + p] + b2[c];
    }
}

// ---------------------------------------------------------------------------
extern "C" void kernel_launch(void* const* d_in, const int* in_sizes, int n_in,
                              void* d_out, int out_size) {
    const float* x        = (const float*)d_in[0];
    const float* se_emb   = (const float*)d_in[1];
    const float* se_w     = (const float*)d_in[2];
    const float* se_b     = (const float*)d_in[3];
    const float* mhf_wr   = (const float*)d_in[4];
    const float* mhf_wi   = (const float*)d_in[5];
    const float* mhf_bias = (const float*)d_in[6];
    const float* sp_emb   = (const float*)d_in[7];
    const float* sp_wr    = (const float*)d_in[8];
    const float* sp_br    = (const float*)d_in[9];
    const float* sp_wi    = (const float*)d_in[10];
    const float* sp_bi    = (const float*)d_in[11];
    const float* gate_w1  = (const float*)d_in[12];
    const float* gate_b1  = (const float*)d_in[13];
    const float* gate_w2  = (const float*)d_in[14];
    const float* gate_b2  = (const float*)d_in[15];
    const float* skip_w   = (const float*)d_in[16];
    const float* skip_b   = (const float*)d_in[17];
    const float* norm_g   = (const float*)d_in[18];
    const float* norm_b   = (const float*)d_in[19];
    const float* mlp_w1   = (const float*)d_in[20];
    const float* mlp_b1   = (const float*)d_in[21];
    const float* mlp_w2   = (const float*)d_in[22];
    const float* mlp_b2   = (const float*)d_in[23];
    float* out = (float*)d_out;

    cudaFuncSetAttribute(k_fwd, cudaFuncAttributeMaxDynamicSharedMemorySize, FWD_SMEM);
    cudaFuncSetAttribute(k_mlp, cudaFuncAttributeMaxDynamicSharedMemorySize, MLP_SMEM);

    k_zero<<<(BB*NPS + 255)/256, 256>>>();
    k_table<<<(NPS*CC + 255)/256, 256>>>(se_emb, se_w, se_b);
    k_hash<<<BB*HH, 128>>>(x);
    k_fwd<<<BB*CC, 256, FWD_SMEM>>>(x);
    k_fidx<<<1, 32>>>();
    k_spat<<<BB, 256>>>();
    k_coef<<<BB*CC, 256>>>(mhf_wr, mhf_wi, mhf_bias, sp_emb, sp_wr, sp_br, sp_wi, sp_bi);
    k_gate<<<1, 512>>>(gate_w1, gate_b1, gate_w2, gate_b2);
    k_y<<<BB*256, 256>>>(x, skip_w, skip_b);
    k_stats<<<1, 32>>>();
    k_mlp<<<BB*256, 256, MLP_SMEM>>>(norm_g, norm_b, mlp_w1, mlp_b1, mlp_w2, mlp_b2, out);
}

// round 7
// speedup vs baseline: 1.3898x; 1.3415x over previous
#include <cuda_runtime.h>
#include <math.h>

#define BB 8
#define CC 64
#define HH 128
#define WW 128
#define HW (HH*WW)
#define MX 32
#define MY 17
#define MXY (MX*MY)
#define NPS 10000
#define NPF 5000
#define EDS 64
#define EDF 32
#define NH 4
#define OPH 16

#define MLP_SMEM ((64*128 + 64*64 + 128*64)*4)    /* 81920 B */
#define FWD_SMEM (32768 + 17408 + 1024 + 1024 + 2048)  /* 54272 B */

typedef unsigned long long ull;
__device__ __forceinline__ ull pk(float x, float y){
    ull r; asm("mov.b64 %0, {%1,%2};" : "=l"(r) : "f"(x), "f"(y)); return r;
}
__device__ __forceinline__ void upk(ull v, float& x, float& y){
    asm("mov.b64 {%0,%1}, %2;" : "=f"(x), "=f"(y) : "l"(v));
}
__device__ __forceinline__ ull ffma2(ull a, ull b, ull c){
    ull d; asm("fma.rn.f32x2 %0, %1, %2, %3;" : "=l"(d) : "l"(a), "l"(b), "l"(c)); return d;
}

// ---------------- scratch (static device globals; no runtime alloc) ----------
__device__ float  g_table[NPS*CC];
__device__ int    g_idx[BB*HW];
__device__ int    g_hist[BB*NPS];
__device__ float2 g_lo[BB*CC*MXY];
__device__ double g_magsum[BB];
__device__ int    g_fidx[BB];
__device__ float  g_spat[BB*CC];
__device__ float  g_mhfm[BB*CC];
__device__ float  g_specm[BB*CC];
__device__ float  g_mhf[BB*CC*HW];
__device__ float  g_spec[BB*CC*HW];
__device__ float  g_y[BB*CC*HW];
__device__ double g_ysum[BB];
__device__ double g_ysq[BB];
__device__ float  g_gw[BB*3];
__device__ float  g_mu[BB];
__device__ float  g_rstd[BB];

// table[p][c] = sum_e se_emb[p][e]*se_w[e][c] + se_b[c]   (+ zero-init fold)
__global__ void k_table(const float* __restrict__ se_emb,
                        const float* __restrict__ se_w,
                        const float* __restrict__ se_b) {
    int t = blockIdx.x*256 + threadIdx.x;
    if (t < BB*NPS) g_hist[t] = 0;
    if (t < BB) { g_magsum[t] = 0.0; g_ysum[t] = 0.0; g_ysq[t] = 0.0; }
    if (t >= NPS*CC) return;
    int c = t & 63, p = t >> 6;
    float acc = se_b[c];
    const float* er = se_emb + p*EDS;
    #pragma unroll 8
    for (int e = 0; e < EDS; e++) acc += er[e] * se_w[e*CC + c];
    g_table[t] = acc;
}

// spatial hash -> idx[b][pix], plus histogram. Separable box filter.
__global__ void k_hash(const float* __restrict__ x) {
    int bid = blockIdx.x;
    int b = bid >> 7, h = bid & 127;
    int w = threadIdx.x;
    int hm = max(h-1, 0), hp = min(h+1, HH-1);
    int wm = max(w-1, 0), wp = min(w+1, WW-1);
    __shared__ int sv[2][128];
    const float* xb = x + (size_t)b*CC*HW;
    float acc = 0.f;
    for (int c = 0; c < CC; c++) {
        const float* xc = xb + c*HW;
        int V = (int)(xc[hm*WW + w]*100.0f)
              + (int)(xc[h *WW + w]*100.0f)
              + (int)(xc[hp*WW + w]*100.0f);
        int* buf = sv[c & 1];
        buf[w] = V;
        __syncthreads();
        int hv = buf[wm] + buf[w] + buf[wp];
        acc += (float)(abs(hv) % NPS);
    }
    int idx = (int)(acc * 0.015625f);
    g_idx[b*HW + h*WW + w] = idx;
    atomicAdd(&g_hist[b*NPS + idx], 1);
}

// spatial mean via histogram
__global__ void k_spat() {
    int b = blockIdx.x;
    int tid = threadIdx.x;
    int c = tid & 63, rep = tid >> 6;   // 16 reps
    float acc = 0.f;
    const int* hb = g_hist + b*NPS;
    for (int n = rep; n < NPS; n += 16)
        acc += (float)hb[n] * g_table[n*CC + c];
    __shared__ float red[1024];
    red[tid] = acc; __syncthreads();
    if (tid < 64) {
        float s = 0.f;
        #pragma unroll
        for (int r = 0; r < 16; r++) s += red[r*64 + c];
        g_spat[b*CC + c] = s * (1.0f/16384.0f);
    }
}

// forward low-mode DFT
__global__ void k_fwd(const float* __restrict__ x) {
    extern __shared__ float sm[];
    float*  xs  = sm;                        // 64*128 rotated tile chunk
    float2* T   = (float2*)(sm + 8192);      // 128*17
    float2* twp = T + 2176;
    float2* twm = twp + 128;
    double* red = (double*)(twm + 128);

    int bc = blockIdx.x, b = bc >> 6;
    int tid = threadIdx.x;
    for (int t = tid; t < 128; t += 256) {
        float s, c; sincospif(t * (1.0f/64.0f), &s, &c);
        twp[t] = make_float2(c, s);
        twm[t] = make_float2(c, -s);
    }
    __syncthreads();
    const float* xp = x + (size_t)bc*HW;
    int r = tid & 63, q = tid >> 6;
    int k0 = (q == 0) ? 0 : (4*q + 1);

    for (int chunk = 0; chunk < 2; chunk++) {
        for (int o = tid; o < 8192; o += 256) {
            int rr = o >> 7, w = o & 127;
            xs[rr*128 + ((w + rr) & 127)] = xp[(size_t)(chunk*64 + rr)*WW + w];
        }
        __syncthreads();
        ull a0 = 0, a1 = 0, a2 = 0, a3 = 0, a4 = 0;
        int i0 = 0, i1 = 0, i2 = 0, i3 = 0, i4 = 0;
        for (int w = 0; w < 128; w++) {
            float v = xs[r*128 + ((w + r) & 127)];
            ull v2 = pk(v, v);
            float2 e;
            e = twm[i0]; a0 = ffma2(v2, pk(e.x, e.y), a0);
            e = twm[i1]; a1 = ffma2(v2, pk(e.x, e.y), a1);
            e = twm[i2]; a2 = ffma2(v2, pk(e.x, e.y), a2);
            e = twm[i3]; a3 = ffma2(v2, pk(e.x, e.y), a3);
            if (q == 0) { e = twm[i4]; a4 = ffma2(v2, pk(e.x, e.y), a4); }
            i0 = (i0 + k0)     & 127;
            i1 = (i1 + k0 + 1) & 127;
            i2 = (i2 + k0 + 2) & 127;
            i3 = (i3 + k0 + 3) & 127;
            i4 = (i4 + 4)      & 127;
        }
        int h = chunk*64 + r;
        float cr, ci;
        upk(a0, cr, ci); T[h*17 + k0    ] = make_float2(cr, ci);
        upk(a1, cr, ci); T[h*17 + k0 + 1] = make_float2(cr, ci);
        upk(a2, cr, ci); T[h*17 + k0 + 2] = make_float2(cr, ci);
        upk(a3, cr, ci); T[h*17 + k0 + 3] = make_float2(cr, ci);
        if (q == 0) { upk(a4, cr, ci); T[h*17 + 4] = make_float2(cr, ci); }
        __syncthreads();
    }

    float msum = 0.f;
    if (tid < 136) {
        int kxg = tid / 17, ky = tid % 17;
        float cr[4] = {0,0,0,0}, ci[4] = {0,0,0,0};
        for (int h = 0; h < 128; h++) {
            float2 tv = T[h*17 + ky];
            #pragma unroll
            for (int u = 0; u < 4; u++) {
                float2 e = twp[((kxg*4 + u)*h) & 127];
                cr[u] += tv.x*e.x + tv.y*e.y;
                ci[u] += tv.y*e.x - tv.x*e.y;
            }
        }
        #pragma unroll
        for (int u = 0; u < 4; u++) {
            float a = cr[u]*0.0078125f, bb = ci[u]*0.0078125f;
            g_lo[bc*MXY + (kxg*4 + u)*17 + ky] = make_float2(a, bb);
            msum += sqrtf(a*a + bb*bb);
        }
    }
    red[tid] = (double)msum; __syncthreads();
    for (int s = 128; s > 0; s >>= 1) {
        if (tid < s) red[tid] += red[tid+s];
        __syncthreads();
    }
    if (tid == 0) atomicAdd(&g_magsum[b], red[0]);
}

__global__ void k_fidx() {
    int b = threadIdx.x;
    if (b < BB) {
        float mag = (float)(g_magsum[b] / (double)(CC*MXY));
        g_fidx[b] = ((int)(mag * 1000.0f)) % NPF;
    }
}

// per (b,c): frequency filter + spec coefficients, then inverse low-mode DFTs
__global__ void k_coef(const float* __restrict__ wr, const float* __restrict__ wi,
                       const float* __restrict__ mhf_bias,
                       const float* __restrict__ sp_emb,
                       const float* __restrict__ sp_wr, const float* __restrict__ sp_br,
                       const float* __restrict__ sp_wi, const float* __restrict__ sp_bi) {
    int bc = blockIdx.x; int b = bc >> 6, c = bc & 63;
    int hc = c >> 4, oc = c & 15;
    int tid = threadIdx.x;
    __shared__ float2 Fm[MXY], Fs[MXY];
    __shared__ float2 Gm[128*18], Gs[128*18];     // padded stride 18 for ky-pair LDS.128
    __shared__ float4 twc[128];                   // (cos, sin, -sin, cos)
    __shared__ float2 twp[128];
    __shared__ float fes[EDF];
    for (int t = tid; t < 128; t += 256) {
        float s, co; sincospif(t * (1.0f/64.0f), &s, &co);
        twc[t] = make_float4(co, s, -s, co);
        twp[t] = make_float2(co, s);
    }
    if (tid < EDF) fes[tid] = sp_emb[g_fidx[b]*EDF + tid];
    __syncthreads();

    const float2* lob = g_lo + b*CC*MXY;
    const float* wrb = wr + (size_t)(hc*CC*OPH + oc)*MXY;
    const float* wib = wi + (size_t)(hc*CC*OPH + oc)*MXY;
    for (int o = tid; o < MXY; o += 256) {
        float mr = 0.f, mi = 0.f;
        for (int i = 0; i < CC; i++) {
            float2 l = lob[i*MXY + o];
            float a = wrb[(size_t)i*OPH*MXY + o];
            float bb = wib[(size_t)i*OPH*MXY + o];
            mr += l.x*a - l.y*bb;
            mi += l.x*bb + l.y*a;
        }
        Fm[o] = make_float2(mr, mi);
        float sr = sp_br[c*MXY + o], si = sp_bi[c*MXY + o];
        for (int e = 0; e < EDF; e++) {
            float f = fes[e];
            sr += f * sp_wr[(size_t)e*(CC*MXY) + c*MXY + o];
            si += f * sp_wi[(size_t)e*(CC*MXY) + c*MXY + o];
        }
        Fs[o] = make_float2(sr, si);
        if (o == 0) {
            g_mhfm[bc]  = mr * 0.0078125f + mhf_bias[c];
            g_specm[bc] = sr * 0.0078125f;
        }
    }
    __syncthreads();
    // G[h,ky] = sum_kx F e^{+2pi i kx h/128}
    for (int o = tid; o < 128*MY; o += 256) {
        int h = o/17, ky = o%17;
        ull gm = 0, gs = 0;
        int ti = 0;
        for (int kx = 0; kx < MX; kx++) {
            float4 tw4 = twc[ti];
            ti = (ti + h) & 127;
            ull ep = pk(tw4.x, tw4.y), en = pk(tw4.z, tw4.w);
            float2 fm = Fm[kx*17 + ky], fs = Fs[kx*17 + ky];
            gm = ffma2(pk(fm.x, fm.x), ep, gm);
            gm = ffma2(pk(fm.y, fm.y), en, gm);
            gs = ffma2(pk(fs.x, fs.x), ep, gs);
            gs = ffma2(pk(fs.y, fs.y), en, gs);
        }
        float a, bb;
        upk(gm, a, bb); Gm[h*18 + ky] = make_float2(a, bb);
        upk(gs, a, bb); Gs[h*18 + ky] = make_float2(a, bb);
    }
    __syncthreads();
    // stage B: out[h,w] = (1/128)[ReG0 + 2*sum_ky(ReG cos - ImG sin)]
    int w = tid & 127;
    int hbase = (tid >> 7) * 64;
    ull cs[17];
    cs[0] = pk(1.f, 0.f);
    #pragma unroll
    for (int ky = 1; ky < 17; ky++) {
        float2 e = twp[(ky*w) & 127];
        cs[ky] = pk(2.f*e.x, -2.f*e.y);
    }
    float bias = mhf_bias[c];
    float* mout = g_mhf  + (size_t)bc*HW;
    float* sout = g_spec + (size_t)bc*HW;
    for (int h = hbase; h < hbase + 64; h++) {
        const float4* Gmr4 = (const float4*)(Gm + h*18);
        const float4* Gsr4 = (const float4*)(Gs + h*18);
        ull am = 0, as = 0;
        #pragma unroll
        for (int kp = 0; kp < 8; kp++) {
            float4 g2 = Gmr4[kp];             // ky=2kp, 2kp+1
            am = ffma2(pk(g2.x, g2.y), cs[2*kp],   am);
            am = ffma2(pk(g2.z, g2.w), cs[2*kp+1], am);
            float4 s2 = Gsr4[kp];
            as = ffma2(pk(s2.x, s2.y), cs[2*kp],   as);
            as = ffma2(pk(s2.z, s2.w), cs[2*kp+1], as);
        }
        {
            float2 g = Gm[h*18 + 16];
            am = ffma2(pk(g.x, g.y), cs[16], am);
            float2 s = Gs[h*18 + 16];
            as = ffma2(pk(s.x, s.y), cs[16], as);
        }
        float m0, m1, s0, s1;
        upk(am, m0, m1); upk(as, s0, s1);
        mout[h*WW + w] = (m0 + m1) * 0.0078125f + bias;
        sout[h*WW + w] = (s0 + s1) * 0.0078125f;
    }
}

__global__ void k_gate(const float* __restrict__ gw1, const float* __restrict__ gb1,
                       const float* __restrict__ gw2, const float* __restrict__ gb2) {
    __shared__ float gi[BB*192];
    __shared__ float h1[BB*64];
    int tid = threadIdx.x;
    for (int o = tid; o < BB*192; o += 512) {
        int b = o/192, k = o%192;
        float v;
        if (k < 64)       v = g_spat[b*64 + k];
        else if (k < 128) v = g_mhfm[b*64 + k - 64];
        else              v = g_specm[b*64 + k - 128];
        gi[o] = v;
    }
    __syncthreads();
    {
        int b = tid >> 6, j = tid & 63;
        float a = gb1[j];
        for (int k = 0; k < 192; k++) a += gi[b*192 + k] * gw1[k*64 + j];
        h1[tid] = 0.5f*a*(1.0f + erff(a*0.70710678118654752f));
    }
    __syncthreads();
    if (tid < BB) {
        int b = tid;
        float l[3];
        #pragma unroll
        for (int m = 0; m < 3; m++) {
            float a = gb2[m];
            for (int j = 0; j < 64; j++) a += h1[b*64 + j] * gw2[j*3 + m];
            l[m] = a;
        }
        float mx = fmaxf(l[0], fmaxf(l[1], l[2]));
        float e0 = expf(l[0]-mx), e1 = expf(l[1]-mx), e2 = expf(l[2]-mx);
        float inv = 1.0f/(e0+e1+e2);
        g_gw[b*3+0] = e0*inv; g_gw[b*3+1] = e1*inv; g_gw[b*3+2] = e2*inv;
    }
}

// y = gate-weighted fuse + skip conv + skip_b; accumulate LN stats
__global__ void k_y(const float* __restrict__ x,
                    const float* __restrict__ skip_w,
                    const float* __restrict__ skip_b) {
    int bx = blockIdx.x;
    int b = bx >> 8, tile = bx & 255;
    int pbase = tile * 64;
    int tid = threadIdx.x;
    __shared__ float buf[64*65];
    __shared__ float ys[64*64];
    __shared__ int idxs[64];
    __shared__ float red[256], redq[256];

    if (tid < 64) idxs[tid] = g_idx[b*HW + pbase + tid];
    for (int o = tid; o < 4096; o += 256) {
        int i = o >> 6, p = o & 63;
        buf[i*64 + p] = x[((size_t)(b*64 + i))*HW + pbase + p];
    }
    __syncthreads();
    // skip 1x1 conv: thread = 4 pixels x 4 channels (c-pair vectorized)
    {
        int pg = tid & 15, cg = tid >> 4;
        ull acc[4][2];
        #pragma unroll
        for (int px = 0; px < 4; px++) { acc[px][0] = 0; acc[px][1] = 0; }
        const float4* xrow;
        for (int i = 0; i < 64; i++) {
            xrow = (const float4*)(buf + i*64 + pg*4);
            float4 xv = xrow[0];
            ull x0 = pk(xv.x, xv.x), x1 = pk(xv.y, xv.y),
                x2 = pk(xv.z, xv.z), x3 = pk(xv.w, xv.w);
            float4 wv = __ldg((const float4*)(skip_w + i*64 + cg*4));
            ull wA = pk(wv.x, wv.y), wB = pk(wv.z, wv.w);
            acc[0][0] = ffma2(x0, wA, acc[0][0]); acc[0][1] = ffma2(x0, wB, acc[0][1]);
            acc[1][0] = ffma2(x1, wA, acc[1][0]); acc[1][1] = ffma2(x1, wB, acc[1][1]);
            acc[2][0] = ffma2(x2, wA, acc[2][0]); acc[2][1] = ffma2(x2, wB, acc[2][1]);
            acc[3][0] = ffma2(x3, wA, acc[3][0]); acc[3][1] = ffma2(x3, wB, acc[3][1]);
        }
        #pragma unroll
        for (int px = 0; px < 4; px++) {
            int p = pg*4 + px;
            #pragma unroll
            for (int u = 0; u < 2; u++) {
                float v0, v1; upk(acc[px][u], v0, v1);
                ys[(cg*4 + 2*u    )*64 + p] = v0;
                ys[(cg*4 + 2*u + 1)*64 + p] = v1;
            }
        }
    }
    __syncthreads();
    for (int o = tid; o < 4096; o += 256) {
        int p = o >> 6, cc2 = o & 63;
        buf[p*65 + cc2] = g_table[idxs[p]*CC + cc2];
    }
    __syncthreads();
    float ga = g_gw[b*3], gbt = g_gw[b*3+1], gm = g_gw[b*3+2];
    float lsum = 0.f, lsq = 0.f;
    for (int o = tid; o < 4096; o += 256) {
        int c = o >> 6, p = o & 63;
        size_t gidx = ((size_t)(b*64 + c))*HW + pbase + p;
        float yv = ga*buf[p*65 + c] + gbt*g_mhf[gidx] + gm*g_spec[gidx]
                 + ys[c*64 + p] + skip_b[c];
        g_y[gidx] = yv;
        lsum += yv; lsq += yv*yv;
    }
    red[tid] = lsum; redq[tid] = lsq; __syncthreads();
    for (int s = 128; s > 0; s >>= 1) {
        if (tid < s) { red[tid] += red[tid+s]; redq[tid] += redq[tid+s]; }
        __syncthreads();
    }
    if (tid == 0) {
        atomicAdd(&g_ysum[b], (double)red[0]);
        atomicAdd(&g_ysq[b],  (double)redq[0]);
    }
}

__global__ void k_stats() {
    int b = threadIdx.x;
    if (b < BB) {
        double n = (double)(CC*HW);
        double mu = g_ysum[b] / n;
        double var = g_ysq[b] / n - mu*mu;
        g_mu[b] = (float)mu;
        g_rstd[b] = (float)(1.0 / sqrt(var + 1e-5));
    }
}

// layernorm + MLP + residual; 4-pixel register blocking both phases
__global__ void k_mlp(const float* __restrict__ norm_g, const float* __restrict__ norm_b,
                      const float* __restrict__ w1, const float* __restrict__ b1,
                      const float* __restrict__ w2, const float* __restrict__ b2,
                      float* __restrict__ out) {
    extern __shared__ float sm[];
    float* w12 = sm;               // 8192
    float* yns = sm + 8192;        // 4096: yn [c][p], later MLP out
    float* hs  = sm + 8192 + 4096; // 8192: hidden [j][p]
    int bx = blockIdx.x;
    int b = bx >> 8, tile = bx & 255;
    int pbase = tile * 64;
    int tid = threadIdx.x;

    for (int o = tid; o < 8192; o += 256) w12[o] = w1[o];
    float mu = g_mu[b], rstd = g_rstd[b];
    for (int o = tid; o < 4096; o += 256) {
        int c = o >> 6, p = o & 63;
        float yv = g_y[((size_t)(b*64 + c))*HW + pbase + p];
        yns[c*64 + p] = (yv - mu)*rstd*norm_g[c] + norm_b[c];
    }
    __syncthreads();
    // phase 1: thread = 4 pixels x 8 j  (16 pg x 16 jg)
    {
        int pg = tid & 15, jg = tid >> 4;
        ull acc[4][4];
        #pragma unroll
        for (int px = 0; px < 4; px++)
            #pragma unroll
            for (int u = 0; u < 4; u++) acc[px][u] = 0;
        for (int c = 0; c < 64; c++) {
            float4 yv4 = *(const float4*)(yns + c*64 + pg*4);
            ull y0 = pk(yv4.x, yv4.x), y1 = pk(yv4.y, yv4.y),
                y2 = pk(yv4.z, yv4.z), y3 = pk(yv4.w, yv4.w);
            const float4* wrow = (const float4*)(w12 + c*128 + jg*8);
            float4 wa = wrow[0], wb = wrow[1];
            ull w0 = pk(wa.x, wa.y), w1p = pk(wa.z, wa.w),
                w2p = pk(wb.x, wb.y), w3 = pk(wb.z, wb.w);
            acc[0][0] = ffma2(y0, w0, acc[0][0]); acc[0][1] = ffma2(y0, w1p, acc[0][1]);
            acc[0][2] = ffma2(y0, w2p, acc[0][2]); acc[0][3] = ffma2(y0, w3, acc[0][3]);
            acc[1][0] = ffma2(y1, w0, acc[1][0]); acc[1][1] = ffma2(y1, w1p, acc[1][1]);
            acc[1][2] = ffma2(y1, w2p, acc[1][2]); acc[1][3] = ffma2(y1, w3, acc[1][3]);
            acc[2][0] = ffma2(y2, w0, acc[2][0]); acc[2][1] = ffma2(y2, w1p, acc[2][1]);
            acc[2][2] = ffma2(y2, w2p, acc[2][2]); acc[2][3] = ffma2(y2, w3, acc[2][3]);
            acc[3][0] = ffma2(y3, w0, acc[3][0]); acc[3][1] = ffma2(y3, w1p, acc[3][1]);
            acc[3][2] = ffma2(y3, w2p, acc[3][2]); acc[3][3] = ffma2(y3, w3, acc[3][3]);
        }
        int j0 = jg*8;
        #pragma unroll
        for (int px = 0; px < 4; px++) {
            int p = pg*4 + px;
            #pragma unroll
            for (int u = 0; u < 4; u++) {
                float v0, v1; upk(acc[px][u], v0, v1);
                int j = j0 + 2*u;
                float a0 = v0 + b1[j], a1 = v1 + b1[j+1];
                hs[j*64 + p]     = 0.5f*a0*(1.0f + erff(a0*0.70710678118654752f));
                hs[(j+1)*64 + p] = 0.5f*a1*(1.0f + erff(a1*0.70710678118654752f));
            }
        }
    }
    __syncthreads();
    for (int o = tid; o < 8192; o += 256) w12[o] = w2[o];
    __syncthreads();
    // phase 2: thread = 4 pixels x 4 c  (16 pg x 16 cg)
    {
        int pg = tid & 15, cg = tid >> 4;
        ull acc2[4][2];
        #pragma unroll
        for (int px = 0; px < 4; px++) { acc2[px][0] = 0; acc2[px][1] = 0; }
        for (int j = 0; j < 128; j++) {
            float4 hv4 = *(const float4*)(hs + j*64 + pg*4);
            ull h0 = pk(hv4.x, hv4.x), h1 = pk(hv4.y, hv4.y),
                h2 = pk(hv4.z, hv4.z), h3 = pk(hv4.w, hv4.w);
            float4 wv = *(const float4*)(w12 + j*64 + cg*4);
            ull wA = pk(wv.x, wv.y), wB = pk(wv.z, wv.w);
            acc2[0][0] = ffma2(h0, wA, acc2[0][0]); acc2[0][1] = ffma2(h0, wB, acc2[0][1]);
            acc2[1][0] = ffma2(h1, wA, acc2[1][0]); acc2[1][1] = ffma2(h1, wB, acc2[1][1]);
            acc2[2][0] = ffma2(h2, wA, acc2[2][0]); acc2[2][1] = ffma2(h2, wB, acc2[2][1]);
            acc2[3][0] = ffma2(h3, wA, acc2[3][0]); acc2[3][1] = ffma2(h3, wB, acc2[3][1]);
        }
        __syncthreads();   // yns reads (phase 1) complete
        #pragma unroll
        for (int px = 0; px < 4; px++) {
            int p = pg*4 + px;
            #pragma unroll
            for (int u = 0; u < 2; u++) {
                float v0, v1; upk(acc2[px][u], v0, v1);
                yns[(cg*4 + 2*u    )*64 + p] = v0;
                yns[(cg*4 + 2*u + 1)*64 + p] = v1;
            }
        }
    }
    __syncthreads();
    for (int o = tid; o < 4096; o += 256) {
        int c = o >> 6, p = o & 63;
        size_t gi2 = ((size_t)(b*64 + c))*HW + pbase + p;
        out[gi2] = g_y[gi2] + yns[c*64 + p] + b2[c];
    }
}

// ---------------------------------------------------------------------------
extern "C" void kernel_launch(void* const* d_in, const int* in_sizes, int n_in,
                              void* d_out, int out_size) {
    const float* x        = (const float*)d_in[0];
    const float* se_emb   = (const float*)d_in[1];
    const float* se_w     = (const float*)d_in[2];
    const float* se_b     = (const float*)d_in[3];
    const float* mhf_wr   = (const float*)d_in[4];
    const float* mhf_wi   = (const float*)d_in[5];
    const float* mhf_bias = (const float*)d_in[6];
    const float* sp_emb   = (const float*)d_in[7];
    const float* sp_wr    = (const float*)d_in[8];
    const float* sp_br    = (const float*)d_in[9];
    const float* sp_wi    = (const float*)d_in[10];
    const float* sp_bi    = (const float*)d_in[11];
    const float* gate_w1  = (const float*)d_in[12];
    const float* gate_b1  = (const float*)d_in[13];
    const float* gate_w2  = (const float*)d_in[14];
    const float* gate_b2  = (const float*)d_in[15];
    const float* skip_w   = (const float*)d_in[16];
    const float* skip_b   = (const float*)d_in[17];
    const float* norm_g   = (const float*)d_in[18];
    const float* norm_b   = (const float*)d_in[19];
    const float* mlp_w1   = (const float*)d_in[20];
    const float* mlp_b1   = (const float*)d_in[21];
    const float* mlp_w2   = (const float*)d_in[22];
    const float* mlp_b2   = (const float*)d_in[23];
    float* out = (float*)d_out;

    cudaFuncSetAttribute(k_fwd, cudaFuncAttributeMaxDynamicSharedMemorySize, FWD_SMEM);
    cudaFuncSetAttribute(k_mlp, cudaFuncAttributeMaxDynamicSharedMemorySize, MLP_SMEM);

    k_table<<<(NPS*CC + 255)/256, 256>>>(se_emb, se_w, se_b);
    k_hash<<<BB*HH, 128>>>(x);
    k_fwd<<<BB*CC, 256, FWD_SMEM>>>(x);
    k_fidx<<<1, 32>>>();
    k_spat<<<BB, 1024>>>();
    k_coef<<<BB*CC, 256>>>(mhf_wr, mhf_wi, mhf_bias, sp_emb, sp_wr, sp_br, sp_wi, sp_bi);
    k_gate<<<1, 512>>>(gate_w1, gate_b1, gate_w2, gate_b2);
    k_y<<<BB*256, 256>>>(x, skip_w, skip_b);
    k_stats<<<1, 32>>>();
    k_mlp<<<BB*256, 256, MLP_SMEM>>>(norm_g, norm_b, mlp_w1, mlp_b1, mlp_w2, mlp_b2, out);
}

// round 9
// speedup vs baseline: 1.7221x; 1.2391x over previous
#include <cuda_runtime.h>
#include <math.h>

#define BB 8
#define CC 64
#define HH 128
#define WW 128
#define HW (HH*WW)
#define MX 32
#define MY 17
#define MXY (MX*MY)
#define NPS 10000
#define NPF 5000
#define EDS 64
#define EDF 32
#define NH 4
#define OPH 16

#define MLP_SMEM ((64*128 + 64*64 + 128*64)*4)    /* 81920 B */
#define FWD_SMEM (32768 + 17408 + 1024 + 1024 + 2048)  /* 54272 B */

typedef unsigned long long ull;
__device__ __forceinline__ ull pk(float x, float y){
    ull r; asm("mov.b64 %0, {%1,%2};" : "=l"(r) : "f"(x), "f"(y)); return r;
}
__device__ __forceinline__ void upk(ull v, float& x, float& y){
    asm("mov.b64 {%0,%1}, %2;" : "=f"(x), "=f"(y) : "l"(v));
}
__device__ __forceinline__ ull ffma2(ull a, ull b, ull c){
    ull d; asm("fma.rn.f32x2 %0, %1, %2, %3;" : "=l"(d) : "l"(a), "l"(b), "l"(c)); return d;
}

// ---------------- scratch (static device globals; no runtime alloc) ----------
__device__ float  g_table[NPS*CC];
__device__ int    g_idx[BB*HW];
__device__ int    g_hist[BB*NPS];
__device__ float2 g_lo[BB*CC*MXY];
__device__ double g_magpart[BB*CC];
__device__ float  g_spat[BB*CC];
__device__ float  g_mhfm[BB*CC];
__device__ float  g_specm[BB*CC];
__device__ float  g_mhf[BB*CC*HW];
__device__ float  g_spec[BB*CC*HW];
__device__ float  g_y[BB*CC*HW];
__device__ double g_ysum[BB];
__device__ double g_ysq[BB];
__device__ float  g_gw[BB*3];

// table[p][c] = sum_e se_emb[p][e]*se_w[e][c] + se_b[c]   (+ zero-init fold)
__global__ void k_table(const float* __restrict__ se_emb,
                        const float* __restrict__ se_w,
                        const float* __restrict__ se_b) {
    int t = blockIdx.x*256 + threadIdx.x;
    if (t < BB*NPS) g_hist[t] = 0;
    if (t < BB) { g_ysum[t] = 0.0; g_ysq[t] = 0.0; }
    if (t >= NPS*CC) return;
    int c = t & 63, p = t >> 6;
    float acc = se_b[c];
    const float* er = se_emb + p*EDS;
    #pragma unroll 8
    for (int e = 0; e < EDS; e++) acc += er[e] * se_w[e*CC + c];
    g_table[t] = acc;
}

// spatial hash -> idx[b][pix], plus histogram.
__global__ void k_hash(const float* __restrict__ x) {
    int bid = blockIdx.x;
    int b = bid >> 7, h = bid & 127;
    int w = threadIdx.x;
    int hm = max(h-1, 0), hp = min(h+1, HH-1);
    int wm = max(w-1, 0), wp = min(w+1, WW-1);
    __shared__ int sv[2][128];
    const float* xb = x + (size_t)b*CC*HW;
    float acc = 0.f;
    for (int c = 0; c < CC; c++) {
        const float* xc = xb + c*HW;
        int V = (int)(xc[hm*WW + w]*100.0f)
              + (int)(xc[h *WW + w]*100.0f)
              + (int)(xc[hp*WW + w]*100.0f);
        int* buf = sv[c & 1];
        buf[w] = V;
        __syncthreads();
        int hv = buf[wm] + buf[w] + buf[wp];
        acc += (float)(abs(hv) % NPS);
    }
    int idx = (int)(acc * 0.015625f);
    g_idx[b*HW + h*WW + w] = idx;
    atomicAdd(&g_hist[b*NPS + idx], 1);
}

// spatial mean via histogram
__global__ void k_spat() {
    int b = blockIdx.x;
    int tid = threadIdx.x;
    int c = tid & 63, rep = tid >> 6;
    float acc = 0.f;
    const int* hb = g_hist + b*NPS;
    for (int n = rep; n < NPS; n += 16)
        acc += (float)hb[n] * g_table[n*CC + c];
    __shared__ float red[1024];
    red[tid] = acc; __syncthreads();
    if (tid < 64) {
        float s = 0.f;
        #pragma unroll
        for (int r = 0; r < 16; r++) s += red[r*64 + c];
        g_spat[b*CC + c] = s * (1.0f/16384.0f);
    }
}

// forward low-mode DFT with w<->128-w folding (stage 1) and
// P/Q + h<->h+64 parity folding (stage 2).
__global__ void k_fwd(const float* __restrict__ x) {
    extern __shared__ float sm[];
    float*  xs  = sm;                        // 64*128 rotated tile chunk
    float2* T   = (float2*)(sm + 8192);      // 128*17
    float2* twp = T + 2176;                  // (cos, sin)
    float2* twm = twp + 128;                 // (cos, -sin)
    double* red = (double*)(twm + 128);      // 256

    int bc = blockIdx.x;
    int tid = threadIdx.x;
    for (int t = tid; t < 128; t += 256) {
        float s, c; sincospif(t * (1.0f/64.0f), &s, &c);
        twp[t] = make_float2(c, s);
        twm[t] = make_float2(c, -s);
    }
    __syncthreads();
    const float* xp = x + (size_t)bc*HW;
    int r = tid & 63, q = tid >> 6;
    int k0 = (q == 0) ? 0 : (4*q + 1);

    for (int chunk = 0; chunk < 2; chunk++) {
        for (int o = tid; o < 8192; o += 256) {
            int rr = o >> 7, w = o & 127;
            xs[rr*128 + ((w + rr) & 127)] = xp[(size_t)(chunk*64 + rr)*WW + w];
        }
        __syncthreads();
        float x0  = xs[r*128 + (r & 127)];
        float x64 = xs[r*128 + ((64 + r) & 127)];
        ull a0 = 0, a1 = 0, a2 = 0, a3 = 0, a4 = 0;
        int i0 = k0, i1 = k0+1, i2 = k0+2, i3 = k0+3, i4 = 4;
        for (int w = 1; w < 64; w++) {
            float v1 = xs[r*128 + ((w + r) & 127)];
            float v2 = xs[r*128 + ((128 - w + r) & 127)];
            ull ab = pk(v1 + v2, v1 - v2);
            float2 e;
            e = twm[i0]; a0 = ffma2(ab, pk(e.x, e.y), a0); i0 = (i0 + k0)     & 127;
            e = twm[i1]; a1 = ffma2(ab, pk(e.x, e.y), a1); i1 = (i1 + k0 + 1) & 127;
            e = twm[i2]; a2 = ffma2(ab, pk(e.x, e.y), a2); i2 = (i2 + k0 + 2) & 127;
            e = twm[i3]; a3 = ffma2(ab, pk(e.x, e.y), a3); i3 = (i3 + k0 + 3) & 127;
            if (q == 0) { e = twm[i4]; a4 = ffma2(ab, pk(e.x, e.y), a4); i4 = (i4 + 4) & 127; }
        }
        int h = chunk*64 + r;
        float cr, ci;
        upk(a0, cr, ci); cr += x0 + (((k0  )&1) ? -x64 : x64); T[h*17 + k0    ] = make_float2(cr, ci);
        upk(a1, cr, ci); cr += x0 + (((k0+1)&1) ? -x64 : x64); T[h*17 + k0 + 1] = make_float2(cr, ci);
        upk(a2, cr, ci); cr += x0 + (((k0+2)&1) ? -x64 : x64); T[h*17 + k0 + 2] = make_float2(cr, ci);
        upk(a3, cr, ci); cr += x0 + (((k0+3)&1) ? -x64 : x64); T[h*17 + k0 + 3] = make_float2(cr, ci);
        if (q == 0) { upk(a4, cr, ci); cr += x0 + x64; T[h*17 + 4] = make_float2(cr, ci); }
        __syncthreads();
    }

    // stage 2: re = P.x + Q.y, im = Q.x - P.y; fold h <-> h+64 by kx parity
    float msum = 0.f;
    if (tid < 136) {
        int kxg = tid / 17, ky = tid % 17;
        int kx0 = kxg*4;
        ull P0=0,Q0=0,P1=0,Q1=0,P2=0,Q2=0,P3=0,Q3=0;
        int i0 = 0, i1 = 0, i2 = 0, i3 = 0;
        for (int h = 0; h < 64; h++) {
            float2 t1 = T[h*17 + ky];
            float2 t2 = T[(h+64)*17 + ky];
            ull SPx = pk(t1.x + t2.x, t1.x + t2.x);
            ull SPy = pk(t1.y + t2.y, t1.y + t2.y);
            ull SMx = pk(t1.x - t2.x, t1.x - t2.x);
            ull SMy = pk(t1.y - t2.y, t1.y - t2.y);
            float2 e;
            e = twp[i0]; i0 = (i0 + kx0    ) & 127; { ull ev = pk(e.x,e.y); P0 = ffma2(SPx, ev, P0); Q0 = ffma2(SPy, ev, Q0); }
            e = twp[i1]; i1 = (i1 + kx0 + 1) & 127; { ull ev = pk(e.x,e.y); P1 = ffma2(SMx, ev, P1); Q1 = ffma2(SMy, ev, Q1); }
            e = twp[i2]; i2 = (i2 + kx0 + 2) & 127; { ull ev = pk(e.x,e.y); P2 = ffma2(SPx, ev, P2); Q2 = ffma2(SPy, ev, Q2); }
            e = twp[i3]; i3 = (i3 + kx0 + 3) & 127; { ull ev = pk(e.x,e.y); P3 = ffma2(SMx, ev, P3); Q3 = ffma2(SMy, ev, Q3); }
        }
        float px, py, qx, qy, a, bb;
        #define FWD_EMIT(Pu, Qu, U) \
            upk(Pu, px, py); upk(Qu, qx, qy); \
            a = (px + qy)*0.0078125f; bb = (qx - py)*0.0078125f; \
            g_lo[bc*MXY + (kx0 + U)*17 + ky] = make_float2(a, bb); \
            msum += sqrtf(a*a + bb*bb);
        FWD_EMIT(P0, Q0, 0)
        FWD_EMIT(P1, Q1, 1)
        FWD_EMIT(P2, Q2, 2)
        FWD_EMIT(P3, Q3, 3)
        #undef FWD_EMIT
    }
    red[tid] = (double)msum; __syncthreads();
    for (int s = 128; s > 0; s >>= 1) {
        if (tid < s) red[tid] += red[tid+s];
        __syncthreads();
    }
    if (tid == 0) g_magpart[bc] = red[0];
}

// per (b,c): filter + spec coefficients, then symmetry-folded inverse DFTs
__global__ void k_coef(const float* __restrict__ wr, const float* __restrict__ wi,
                       const float* __restrict__ mhf_bias,
                       const float* __restrict__ sp_emb,
                       const float* __restrict__ sp_wr, const float* __restrict__ sp_br,
                       const float* __restrict__ sp_wi, const float* __restrict__ sp_bi) {
    int bc = blockIdx.x; int b = bc >> 6, c = bc & 63;
    int hc = c >> 4, oc = c & 15;
    int tid = threadIdx.x;
    __shared__ float2 Fm[MXY], Fs[MXY];
    __shared__ __align__(16) float2 Gm[128*18], Gs[128*18];  // parity-slotted rows
    __shared__ float2 twp[128];
    __shared__ float fes[EDF];
    __shared__ int s_fidx;
    for (int t = tid; t < 128; t += 256) {
        float s, co; sincospif(t * (1.0f/64.0f), &s, &co);
        twp[t] = make_float2(co, s);
    }
    if (tid == 0) {
        double msum = 0.0;
        const double* mp = g_magpart + b*CC;
        for (int i = 0; i < CC; i++) msum += mp[i];
        float mag = (float)(msum / (double)(CC*MXY));
        s_fidx = ((int)(mag * 1000.0f)) % NPF;
    }
    __syncthreads();
    if (tid < EDF) fes[tid] = sp_emb[s_fidx*EDF + tid];
    __syncthreads();

    // phase 1: F coefficients (stored kx*17+ky, like before)
    const float2* lob = g_lo + b*CC*MXY;
    const float* wrb = wr + (size_t)(hc*CC*OPH + oc)*MXY;
    const float* wib = wi + (size_t)(hc*CC*OPH + oc)*MXY;
    for (int o = tid; o < MXY; o += 256) {
        float mr = 0.f, mi = 0.f;
        for (int i = 0; i < CC; i++) {
            float2 l = lob[i*MXY + o];
            float a = wrb[(size_t)i*OPH*MXY + o];
            float bb = wib[(size_t)i*OPH*MXY + o];
            mr += l.x*a - l.y*bb;
            mi += l.x*bb + l.y*a;
        }
        Fm[o] = make_float2(mr, mi);
        float sr = sp_br[c*MXY + o], si = sp_bi[c*MXY + o];
        for (int e = 0; e < EDF; e++) {
            float f = fes[e];
            sr += f * sp_wr[(size_t)e*(CC*MXY) + c*MXY + o];
            si += f * sp_wi[(size_t)e*(CC*MXY) + c*MXY + o];
        }
        Fs[o] = make_float2(sr, si);
        if (o == 0) {
            g_mhfm[bc]  = mr * 0.0078125f + mhf_bias[c];
            g_specm[bc] = sr * 0.0078125f;
        }
    }
    __syncthreads();

    // stage G folded: h-rep in [0,32] x ky -> 4 h outputs per point.
    // P = sum Fx*(c,s), Q = sum Fy*(c,s), parity-split over kx.
    for (int o = tid; o < 33*17; o += 256) {
        int h = o/17, ky = o%17;
        ull Pme=0,Qme=0,Pmo=0,Qmo=0, Pse=0,Qse=0,Pso=0,Qso=0;
        int ti = 0;
        #pragma unroll 4
        for (int kx = 0; kx < MX; kx += 2) {
            {
                float2 e = twp[ti]; ti = (ti + h) & 127;
                ull ev = pk(e.x, e.y);
                float2 fm = Fm[kx*17 + ky], fs = Fs[kx*17 + ky];
                Pme = ffma2(pk(fm.x, fm.x), ev, Pme);
                Qme = ffma2(pk(fm.y, fm.y), ev, Qme);
                Pse = ffma2(pk(fs.x, fs.x), ev, Pse);
                Qse = ffma2(pk(fs.y, fs.y), ev, Qse);
            }
            {
                float2 e = twp[ti]; ti = (ti + h) & 127;
                ull ev = pk(e.x, e.y);
                float2 fm = Fm[(kx+1)*17 + ky], fs = Fs[(kx+1)*17 + ky];
                Pmo = ffma2(pk(fm.x, fm.x), ev, Pmo);
                Qmo = ffma2(pk(fm.y, fm.y), ev, Qmo);
                Pso = ffma2(pk(fs.x, fs.x), ev, Pso);
                Qso = ffma2(pk(fs.y, fs.y), ev, Qso);
            }
        }
        int slot = (ky & 1) ? (10 + (ky >> 1)) : (ky >> 1);
        float pex,pey,qex,qey,pox,poy,qox,qoy;
        #define G_EMIT(G, Pe, Qe, Po, Qo) \
            upk(Pe,pex,pey); upk(Qe,qex,qey); upk(Po,pox,poy); upk(Qo,qox,qoy); \
            { float Px=pex+pox, Py=pey+poy, Qx=qex+qox, Qy=qey+qoy; \
              float Mx=pex-pox, My=pey-poy, Nx=qex-qox, Ny=qey-qoy; \
              G[h*18 + slot]        = make_float2(Px - Qy, Py + Qx); \
              G[(h+64)*18 + slot]   = make_float2(Mx - Ny, My + Nx); \
              if (h) { \
                G[(128-h)*18 + slot] = make_float2(Px + Qy, Qx - Py); \
                G[(64-h)*18 + slot]  = make_float2(Mx + Ny, Nx - My); \
              } }
        G_EMIT(Gm, Pme, Qme, Pmo, Qmo)
        G_EMIT(Gs, Pse, Qse, Pso, Qso)
        #undef G_EMIT
    }
    __syncthreads();

    // stage B folded: per (h, w-rep) accumulate even/odd-ky (A,B) pairs,
    // emit out[w], out[128-w], out[w+64], out[64-w].
    float bias = mhf_bias[c];
    const float sc = 0.0078125f;
    float* mout = g_mhf  + (size_t)bc*HW;
    float* sout = g_spec + (size_t)bc*HW;
    {
        int w = tid & 31;
        int hg = tid >> 5;
        ull cse[9], cso[8];
        cse[0] = pk(1.f, 0.f);
        #pragma unroll
        for (int j = 1; j < 9; j++) {
            float2 e = twp[(2*j*w) & 127];
            cse[j] = pk(2.f*e.x, 2.f*e.y);
        }
        #pragma unroll
        for (int j = 0; j < 8; j++) {
            float2 e = twp[((2*j+1)*w) & 127];
            cso[j] = pk(2.f*e.x, 2.f*e.y);
        }
        for (int i = 0; i < 16; i++) {
            int h = hg*16 + i;
            const float4* Ge4m = (const float4*)(Gm + h*18);
            const float4* Go4m = (const float4*)(Gm + h*18 + 10);
            const float4* Ge4s = (const float4*)(Gs + h*18);
            const float4* Go4s = (const float4*)(Gs + h*18 + 10);
            ull me = 0, mo = 0, se = 0, so = 0;
            #pragma unroll
            for (int j2 = 0; j2 < 4; j2++) {
                float4 g = Ge4m[j2];
                me = ffma2(pk(g.x,g.y), cse[2*j2],   me);
                me = ffma2(pk(g.z,g.w), cse[2*j2+1], me);
                float4 s4 = Ge4s[j2];
                se = ffma2(pk(s4.x,s4.y), cse[2*j2],   se);
                se = ffma2(pk(s4.z,s4.w), cse[2*j2+1], se);
            }
            { float2 g = Gm[h*18 + 8]; me = ffma2(pk(g.x,g.y), cse[8], me);
              float2 s2 = Gs[h*18 + 8]; se = ffma2(pk(s2.x,s2.y), cse[8], se); }
            #pragma unroll
            for (int j2 = 0; j2 < 4; j2++) {
                float4 g = Go4m[j2];
                mo = ffma2(pk(g.x,g.y), cso[2*j2],   mo);
                mo = ffma2(pk(g.z,g.w), cso[2*j2+1], mo);
                float4 s4 = Go4s[j2];
                so = ffma2(pk(s4.x,s4.y), cso[2*j2],   so);
                so = ffma2(pk(s4.z,s4.w), cso[2*j2+1], so);
            }
            float Ae,Be,Ao,Bo;
            upk(me,Ae,Be); upk(mo,Ao,Bo);
            {
                float ap=Ae+Ao, bp=Be+Bo, am=Ae-Ao, bm=Be-Bo;
                mout[h*WW + w]        = (ap - bp)*sc + bias;
                mout[h*WW + 64 + w]   = (am - bm)*sc + bias;
                if (w) {
                    mout[h*WW + 128 - w] = (ap + bp)*sc + bias;
                    mout[h*WW + 64 - w]  = (am + bm)*sc + bias;
                }
            }
            upk(se,Ae,Be); upk(so,Ao,Bo);
            {
                float ap=Ae+Ao, bp=Be+Bo, am=Ae-Ao, bm=Be-Bo;
                sout[h*WW + w]        = (ap - bp)*sc;
                sout[h*WW + 64 + w]   = (am - bm)*sc;
                if (w) {
                    sout[h*WW + 128 - w] = (ap + bp)*sc;
                    sout[h*WW + 64 - w]  = (am + bm)*sc;
                }
            }
        }
    }
    // w = 32 orbit {32, 96}
    if (tid < 128) {
        int h = tid;
        ull cse[9], cso[8];
        cse[0] = pk(1.f, 0.f);
        #pragma unroll
        for (int j = 1; j < 9; j++) {
            float2 e = twp[(2*j*32) & 127];
            cse[j] = pk(2.f*e.x, 2.f*e.y);
        }
        #pragma unroll
        for (int j = 0; j < 8; j++) {
            float2 e = twp[((2*j+1)*32) & 127];
            cso[j] = pk(2.f*e.x, 2.f*e.y);
        }
        const float4* Ge4m = (const float4*)(Gm + h*18);
        const float4* Go4m = (const float4*)(Gm + h*18 + 10);
        const float4* Ge4s = (const float4*)(Gs + h*18);
        const float4* Go4s = (const float4*)(Gs + h*18 + 10);
        ull me = 0, mo = 0, se = 0, so = 0;
        #pragma unroll
        for (int j2 = 0; j2 < 4; j2++) {
            float4 g = Ge4m[j2];
            me = ffma2(pk(g.x,g.y), cse[2*j2],   me);
            me = ffma2(pk(g.z,g.w), cse[2*j2+1], me);
            float4 s4 = Ge4s[j2];
            se = ffma2(pk(s4.x,s4.y), cse[2*j2],   se);
            se = ffma2(pk(s4.z,s4.w), cse[2*j2+1], se);
        }
        { float2 g = Gm[h*18 + 8]; me = ffma2(pk(g.x,g.y), cse[8], me);
          float2 s2 = Gs[h*18 + 8]; se = ffma2(pk(s2.x,s2.y), cse[8], se); }
        #pragma unroll
        for (int j2 = 0; j2 < 4; j2++) {
            float4 g = Go4m[j2];
            mo = ffma2(pk(g.x,g.y), cso[2*j2],   mo);
            mo = ffma2(pk(g.z,g.w), cso[2*j2+1], mo);
            float4 s4 = Go4s[j2];
            so = ffma2(pk(s4.x,s4.y), cso[2*j2],   so);
            so = ffma2(pk(s4.z,s4.w), cso[2*j2+1], so);
        }
        float Ae,Be,Ao,Bo;
        upk(me,Ae,Be); upk(mo,Ao,Bo);
        mout[h*WW + 32] = ((Ae+Ao) - (Be+Bo))*sc + bias;
        mout[h*WW + 96] = ((Ae-Ao) - (Be-Bo))*sc + bias;
        upk(se,Ae,Be); upk(so,Ao,Bo);
        sout[h*WW + 32] = ((Ae+Ao) - (Be+Bo))*sc;
        sout[h*WW + 96] = ((Ae-Ao) - (Be-Bo))*sc;
    }
}

__global__ void k_gate(const float* __restrict__ gw1, const float* __restrict__ gb1,
                       const float* __restrict__ gw2, const float* __restrict__ gb2) {
    __shared__ float gi[BB*192];
    __shared__ float h1[BB*64];
    int tid = threadIdx.x;
    for (int o = tid; o < BB*192; o += 512) {
        int b = o/192, k = o%192;
        float v;
        if (k < 64)       v = g_spat[b*64 + k];
        else if (k < 128) v = g_mhfm[b*64 + k - 64];
        else              v = g_specm[b*64 + k - 128];
        gi[o] = v;
    }
    __syncthreads();
    {
        int b = tid >> 6, j = tid & 63;
        float a = gb1[j];
        for (int k = 0; k < 192; k++) a += gi[b*192 + k] * gw1[k*64 + j];
        h1[tid] = 0.5f*a*(1.0f + erff(a*0.70710678118654752f));
    }
    __syncthreads();
    if (tid < BB) {
        int b = tid;
        float l[3];
        #pragma unroll
        for (int m = 0; m < 3; m++) {
            float a = gb2[m];
            for (int j = 0; j < 64; j++) a += h1[b*64 + j] * gw2[j*3 + m];
            l[m] = a;
        }
        float mx = fmaxf(l[0], fmaxf(l[1], l[2]));
        float e0 = expf(l[0]-mx), e1 = expf(l[1]-mx), e2 = expf(l[2]-mx);
        float inv = 1.0f/(e0+e1+e2);
        g_gw[b*3+0] = e0*inv; g_gw[b*3+1] = e1*inv; g_gw[b*3+2] = e2*inv;
    }
}

// y = gate-weighted fuse + skip conv + skip_b; accumulate LN stats
__global__ void k_y(const float* __restrict__ x,
                    const float* __restrict__ skip_w,
                    const float* __restrict__ skip_b) {
    int bx = blockIdx.x;
    int b = bx >> 8, tile = bx & 255;
    int pbase = tile * 64;
    int tid = threadIdx.x;
    __shared__ float buf[64*65];
    __shared__ float ys[64*64];
    __shared__ int idxs[64];
    __shared__ float red[256], redq[256];

    if (tid < 64) idxs[tid] = g_idx[b*HW + pbase + tid];
    for (int o = tid; o < 4096; o += 256) {
        int i = o >> 6, p = o & 63;
        buf[i*64 + p] = x[((size_t)(b*64 + i))*HW + pbase + p];
    }
    __syncthreads();
    {
        int pg = tid & 15, cg = tid >> 4;
        ull acc[4][2];
        #pragma unroll
        for (int px = 0; px < 4; px++) { acc[px][0] = 0; acc[px][1] = 0; }
        for (int i = 0; i < 64; i++) {
            float4 xv = *(const float4*)(buf + i*64 + pg*4);
            ull x0 = pk(xv.x, xv.x), x1 = pk(xv.y, xv.y),
                x2 = pk(xv.z, xv.z), x3 = pk(xv.w, xv.w);
            float4 wv = __ldg((const float4*)(skip_w + i*64 + cg*4));
            ull wA = pk(wv.x, wv.y), wB = pk(wv.z, wv.w);
            acc[0][0] = ffma2(x0, wA, acc[0][0]); acc[0][1] = ffma2(x0, wB, acc[0][1]);
            acc[1][0] = ffma2(x1, wA, acc[1][0]); acc[1][1] = ffma2(x1, wB, acc[1][1]);
            acc[2][0] = ffma2(x2, wA, acc[2][0]); acc[2][1] = ffma2(x2, wB, acc[2][1]);
            acc[3][0] = ffma2(x3, wA, acc[3][0]); acc[3][1] = ffma2(x3, wB, acc[3][1]);
        }
        #pragma unroll
        for (int px = 0; px < 4; px++) {
            int p = pg*4 + px;
            #pragma unroll
            for (int u = 0; u < 2; u++) {
                float v0, v1; upk(acc[px][u], v0, v1);
                ys[(cg*4 + 2*u    )*64 + p] = v0;
                ys[(cg*4 + 2*u + 1)*64 + p] = v1;
            }
        }
    }
    __syncthreads();
    for (int o = tid; o < 4096; o += 256) {
        int p = o >> 6, cc2 = o & 63;
        buf[p*65 + cc2] = g_table[idxs[p]*CC + cc2];
    }
    __syncthreads();
    float ga = g_gw[b*3], gbt = g_gw[b*3+1], gm = g_gw[b*3+2];
    float lsum = 0.f, lsq = 0.f;
    for (int o = tid; o < 4096; o += 256) {
        int c = o >> 6, p = o & 63;
        size_t gidx = ((size_t)(b*64 + c))*HW + pbase + p;
        float yv = ga*buf[p*65 + c] + gbt*g_mhf[gidx] + gm*g_spec[gidx]
                 + ys[c*64 + p] + skip_b[c];
        g_y[gidx] = yv;
        lsum += yv; lsq += yv*yv;
    }
    red[tid] = lsum; redq[tid] = lsq; __syncthreads();
    for (int s = 128; s > 0; s >>= 1) {
        if (tid < s) { red[tid] += red[tid+s]; redq[tid] += redq[tid+s]; }
        __syncthreads();
    }
    if (tid == 0) {
        atomicAdd(&g_ysum[b], (double)red[0]);
        atomicAdd(&g_ysq[b],  (double)redq[0]);
    }
}

// layernorm + MLP + residual; stats computed per-block (k_stats folded in)
__global__ void k_mlp(const float* __restrict__ norm_g, const float* __restrict__ norm_b,
                      const float* __restrict__ w1, const float* __restrict__ b1,
                      const float* __restrict__ w2, const float* __restrict__ b2,
                      float* __restrict__ out) {
    extern __shared__ float sm[];
    float* w12 = sm;               // 8192
    float* yns = sm + 8192;        // 4096
    float* hs  = sm + 8192 + 4096; // 8192
    __shared__ float s_mu, s_rstd;
    int bx = blockIdx.x;
    int b = bx >> 8, tile = bx & 255;
    int pbase = tile * 64;
    int tid = threadIdx.x;

    if (tid == 0) {
        double n = (double)(CC*HW);
        double mu = g_ysum[b] / n;
        double var = g_ysq[b] / n - mu*mu;
        s_mu = (float)mu;
        s_rstd = (float)(1.0 / sqrt(var + 1e-5));
    }
    for (int o = tid; o < 8192; o += 256) w12[o] = w1[o];
    __syncthreads();
    float mu = s_mu, rstd = s_rstd;
    for (int o = tid; o < 4096; o += 256) {
        int c = o >> 6, p = o & 63;
        float yv = g_y[((size_t)(b*64 + c))*HW + pbase + p];
        yns[c*64 + p] = (yv - mu)*rstd*norm_g[c] + norm_b[c];
    }
    __syncthreads();
    {
        int pg = tid & 15, jg = tid >> 4;
        ull acc[4][4];
        #pragma unroll
        for (int px = 0; px < 4; px++)
            #pragma unroll
            for (int u = 0; u < 4; u++) acc[px][u] = 0;
        for (int c = 0; c < 64; c++) {
            float4 yv4 = *(const float4*)(yns + c*64 + pg*4);
            ull y0 = pk(yv4.x, yv4.x), y1 = pk(yv4.y, yv4.y),
                y2 = pk(yv4.z, yv4.z), y3 = pk(yv4.w, yv4.w);
            const float4* wrow = (const float4*)(w12 + c*128 + jg*8);
            float4 wa = wrow[0], wb = wrow[1];
            ull w0 = pk(wa.x, wa.y), w1p = pk(wa.z, wa.w),
                w2p = pk(wb.x, wb.y), w3 = pk(wb.z, wb.w);
            acc[0][0] = ffma2(y0, w0, acc[0][0]); acc[0][1] = ffma2(y0, w1p, acc[0][1]);
            acc[0][2] = ffma2(y0, w2p, acc[0][2]); acc[0][3] = ffma2(y0, w3, acc[0][3]);
            acc[1][0] = ffma2(y1, w0, acc[1][0]); acc[1][1] = ffma2(y1, w1p, acc[1][1]);
            acc[1][2] = ffma2(y1, w2p, acc[1][2]); acc[1][3] = ffma2(y1, w3, acc[1][3]);
            acc[2][0] = ffma2(y2, w0, acc[2][0]); acc[2][1] = ffma2(y2, w1p, acc[2][1]);
            acc[2][2] = ffma2(y2, w2p, acc[2][2]); acc[2][3] = ffma2(y2, w3, acc[2][3]);
            acc[3][0] = ffma2(y3, w0, acc[3][0]); acc[3][1] = ffma2(y3, w1p, acc[3][1]);
            acc[3][2] = ffma2(y3, w2p, acc[3][2]); acc[3][3] = ffma2(y3, w3, acc[3][3]);
        }
        int j0 = jg*8;
        #pragma unroll
        for (int px = 0; px < 4; px++) {
            int p = pg*4 + px;
            #pragma unroll
            for (int u = 0; u < 4; u++) {
                float v0, v1; upk(acc[px][u], v0, v1);
                int j = j0 + 2*u;
                float a0 = v0 + b1[j], a1 = v1 + b1[j+1];
                hs[j*64 + p]     = 0.5f*a0*(1.0f + erff(a0*0.70710678118654752f));
                hs[(j+1)*64 + p] = 0.5f*a1*(1.0f + erff(a1*0.70710678118654752f));
            }
        }
    }
    __syncthreads();
    for (int o = tid; o < 8192; o += 256) w12[o] = w2[o];
    __syncthreads();
    {
        int pg = tid & 15, cg = tid >> 4;
        ull acc2[4][2];
        #pragma unroll
        for (int px = 0; px < 4; px++) { acc2[px][0] = 0; acc2[px][1] = 0; }
        for (int j = 0; j < 128; j++) {
            float4 hv4 = *(const float4*)(hs + j*64 + pg*4);
            ull h0 = pk(hv4.x, hv4.x), h1 = pk(hv4.y, hv4.y),
                h2 = pk(hv4.z, hv4.z), h3 = pk(hv4.w, hv4.w);
            float4 wv = *(const float4*)(w12 + j*64 + cg*4);
            ull wA = pk(wv.x, wv.y), wB = pk(wv.z, wv.w);
            acc2[0][0] = ffma2(h0, wA, acc2[0][0]); acc2[0][1] = ffma2(h0, wB, acc2[0][1]);
            acc2[1][0] = ffma2(h1, wA, acc2[1][0]); acc2[1][1] = ffma2(h1, wB, acc2[1][1]);
            acc2[2][0] = ffma2(h2, wA, acc2[2][0]); acc2[2][1] = ffma2(h2, wB, acc2[2][1]);
            acc2[3][0] = ffma2(h3, wA, acc2[3][0]); acc2[3][1] = ffma2(h3, wB, acc2[3][1]);
        }
        __syncthreads();
        #pragma unroll
        for (int px = 0; px < 4; px++) {
            int p = pg*4 + px;
            #pragma unroll
            for (int u = 0; u < 2; u++) {
                float v0, v1; upk(acc2[px][u], v0, v1);
                yns[(cg*4 + 2*u    )*64 + p] = v0;
                yns[(cg*4 + 2*u + 1)*64 + p] = v1;
            }
        }
    }
    __syncthreads();
    for (int o = tid; o < 4096; o += 256) {
        int c = o >> 6, p = o & 63;
        size_t gi2 = ((size_t)(b*64 + c))*HW + pbase + p;
        out[gi2] = g_y[gi2] + yns[c*64 + p] + b2[c];
    }
}

// ---------------------------------------------------------------------------
extern "C" void kernel_launch(void* const* d_in, const int* in_sizes, int n_in,
                              void* d_out, int out_size) {
    const float* x        = (const float*)d_in[0];
    const float* se_emb   = (const float*)d_in[1];
    const float* se_w     = (const float*)d_in[2];
    const float* se_b     = (const float*)d_in[3];
    const float* mhf_wr   = (const float*)d_in[4];
    const float* mhf_wi   = (const float*)d_in[5];
    const float* mhf_bias = (const float*)d_in[6];
    const float* sp_emb   = (const float*)d_in[7];
    const float* sp_wr    = (const float*)d_in[8];
    const float* sp_br    = (const float*)d_in[9];
    const float* sp_wi    = (const float*)d_in[10];
    const float* sp_bi    = (const float*)d_in[11];
    const float* gate_w1  = (const float*)d_in[12];
    const float* gate_b1  = (const float*)d_in[13];
    const float* gate_w2  = (const float*)d_in[14];
    const float* gate_b2  = (const float*)d_in[15];
    const float* skip_w   = (const float*)d_in[16];
    const float* skip_b   = (const float*)d_in[17];
    const float* norm_g   = (const float*)d_in[18];
    const float* norm_b   = (const float*)d_in[19];
    const float* mlp_w1   = (const float*)d_in[20];
    const float* mlp_b1   = (const float*)d_in[21];
    const float* mlp_w2   = (const float*)d_in[22];
    const float* mlp_b2   = (const float*)d_in[23];
    float* out = (float*)d_out;

    cudaFuncSetAttribute(k_fwd, cudaFuncAttributeMaxDynamicSharedMemorySize, FWD_SMEM);
    cudaFuncSetAttribute(k_mlp, cudaFuncAttributeMaxDynamicSharedMemorySize, MLP_SMEM);

    k_table<<<(NPS*CC + 255)/256, 256>>>(se_emb, se_w, se_b);
    k_hash<<<BB*HH, 128>>>(x);
    k_fwd<<<BB*CC, 256, FWD_SMEM>>>(x);
    k_spat<<<BB, 1024>>>();
    k_coef<<<BB*CC, 256>>>(mhf_wr, mhf_wi, mhf_bias, sp_emb, sp_wr, sp_br, sp_wi, sp_bi);
    k_gate<<<1, 512>>>(gate_w1, gate_b1, gate_w2, gate_b2);
    k_y<<<BB*256, 256>>>(x, skip_w, skip_b);
    k_mlp<<<BB*256, 256, MLP_SMEM>>>(norm_g, norm_b, mlp_w1, mlp_b1, mlp_w2, mlp_b2, out);
}

// round 14
// speedup vs baseline: 1.7834x; 1.0356x over previous
#include <cuda_runtime.h>
#include <math.h>

#define BB 8
#define CC 64
#define HH 128
#define WW 128
#define HW (HH*WW)
#define MX 32
#define MY 17
#define MXY (MX*MY)
#define NPS 10000
#define NPF 5000
#define EDS 64
#define EDF 32
#define NH 4
#define OPH 16
#define SPART 16
#define SPN (NPS/SPART)   /* 625 */

#define MLP_SMEM ((64*128 + 64*64 + 128*64)*4)    /* 81920 B */
#define FWD_SMEM (32768 + 17408 + 1024 + 1024 + 2048)  /* 54272 B */

typedef unsigned long long ull;
__device__ __forceinline__ ull pk(float x, float y){
    ull r; asm("mov.b64 %0, {%1,%2};" : "=l"(r) : "f"(x), "f"(y)); return r;
}
__device__ __forceinline__ void upk(ull v, float& x, float& y){
    asm("mov.b64 {%0,%1}, %2;" : "=f"(x), "=f"(y) : "l"(v));
}
__device__ __forceinline__ ull ffma2(ull a, ull b, ull c){
    ull d; asm("fma.rn.f32x2 %0, %1, %2, %3;" : "=l"(d) : "l"(a), "l"(b), "l"(c)); return d;
}

// ---------------- scratch (static device globals; no runtime alloc) ----------
__device__ float  g_table[NPS*CC];
__device__ int    g_idx[BB*HW];
__device__ int    g_hist[BB*NPS];
__device__ float2 g_lo[BB*CC*MXY];
__device__ double g_magpart[BB*CC];
__device__ float  g_spart[BB*SPART*CC];
__device__ float  g_mhfm[BB*CC];
__device__ float  g_specm[BB*CC];
__device__ float  g_mhf[BB*CC*HW];
__device__ float  g_spec[BB*CC*HW];
__device__ float  g_y[BB*CC*HW];
__device__ double g_ysum[BB];
__device__ double g_ysq[BB];
__device__ float  g_gw[BB*3];

// table[p][c] = sum_e se_emb[p][e]*se_w[e][c] + se_b[c]   (+ zero-init fold)
__global__ void k_table(const float* __restrict__ se_emb,
                        const float* __restrict__ se_w,
                        const float* __restrict__ se_b) {
    int t = blockIdx.x*256 + threadIdx.x;
    if (t < BB*NPS) g_hist[t] = 0;
    if (t < BB) { g_ysum[t] = 0.0; g_ysq[t] = 0.0; }
    if (t >= NPS*CC) return;
    int c = t & 63, p = t >> 6;
    float acc = se_b[c];
    const float* er = se_emb + p*EDS;
    #pragma unroll 8
    for (int e = 0; e < EDS; e++) acc += er[e] * se_w[e*CC + c];
    g_table[t] = acc;
}

// spatial hash -> idx[b][pix], plus histogram.
__global__ void k_hash(const float* __restrict__ x) {
    int bid = blockIdx.x;
    int b = bid >> 7, h = bid & 127;
    int w = threadIdx.x;
    int hm = max(h-1, 0), hp = min(h+1, HH-1);
    int wm = max(w-1, 0), wp = min(w+1, WW-1);
    __shared__ int sv[2][128];
    const float* xb = x + (size_t)b*CC*HW;
    float acc = 0.f;
    for (int c = 0; c < CC; c++) {
        const float* xc = xb + c*HW;
        int V = (int)(xc[hm*WW + w]*100.0f)
              + (int)(xc[h *WW + w]*100.0f)
              + (int)(xc[hp*WW + w]*100.0f);
        int* buf = sv[c & 1];
        buf[w] = V;
        __syncthreads();
        int hv = buf[wm] + buf[w] + buf[wp];
        acc += (float)(abs(hv) % NPS);
    }
    int idx = (int)(acc * 0.015625f);
    g_idx[b*HW + h*WW + w] = idx;
    atomicAdd(&g_hist[b*NPS + idx], 1);
}

// spatial-mean partials: block = (b, part); part covers 625 histogram rows.
__global__ void k_spat() {
    int bp = blockIdx.x;
    int b = bp >> 4, part = bp & 15;
    int tid = threadIdx.x;
    int c = tid & 63, rep = tid >> 6;   // 4 reps
    int n0 = part*SPN;
    float acc = 0.f;
    const int* hb = g_hist + b*NPS;
    for (int n = n0 + rep; n < n0 + SPN; n += 4) {
        int hv = hb[n];
        if (hv) acc += (float)hv * g_table[n*CC + c];
    }
    __shared__ float red[256];
    red[tid] = acc; __syncthreads();
    if (tid < 64)
        g_spart[(b*SPART + part)*CC + c] =
            red[c] + red[64 + c] + red[128 + c] + red[192 + c];
}

// forward low-mode DFT with w<->128-w folding (stage 1) and
// P/Q + h<->h+64 parity folding (stage 2).
__global__ void k_fwd(const float* __restrict__ x) {
    extern __shared__ float sm[];
    float*  xs  = sm;                        // 64*128 rotated tile chunk
    float2* T   = (float2*)(sm + 8192);      // 128*17
    float2* twp = T + 2176;                  // (cos, sin)
    float2* twm = twp + 128;                 // (cos, -sin)
    double* red = (double*)(twm + 128);      // 256

    int bc = blockIdx.x;
    int tid = threadIdx.x;
    for (int t = tid; t < 128; t += 256) {
        float s, c; sincospif(t * (1.0f/64.0f), &s, &c);
        twp[t] = make_float2(c, s);
        twm[t] = make_float2(c, -s);
    }
    __syncthreads();
    const float* xp = x + (size_t)bc*HW;
    int r = tid & 63, q = tid >> 6;
    int k0 = (q == 0) ? 0 : (4*q + 1);

    for (int chunk = 0; chunk < 2; chunk++) {
        for (int o = tid; o < 8192; o += 256) {
            int rr = o >> 7, w = o & 127;
            xs[rr*128 + ((w + rr) & 127)] = xp[(size_t)(chunk*64 + rr)*WW + w];
        }
        __syncthreads();
        float x0  = xs[r*128 + (r & 127)];
        float x64 = xs[r*128 + ((64 + r) & 127)];
        ull a0 = 0, a1 = 0, a2 = 0, a3 = 0, a4 = 0;
        int i0 = k0, i1 = k0+1, i2 = k0+2, i3 = k0+3, i4 = 4;
        for (int w = 1; w < 64; w++) {
            float v1 = xs[r*128 + ((w + r) & 127)];
            float v2 = xs[r*128 + ((128 - w + r) & 127)];
            ull ab = pk(v1 + v2, v1 - v2);
            float2 e;
            e = twm[i0]; a0 = ffma2(ab, pk(e.x, e.y), a0); i0 = (i0 + k0)     & 127;
            e = twm[i1]; a1 = ffma2(ab, pk(e.x, e.y), a1); i1 = (i1 + k0 + 1) & 127;
            e = twm[i2]; a2 = ffma2(ab, pk(e.x, e.y), a2); i2 = (i2 + k0 + 2) & 127;
            e = twm[i3]; a3 = ffma2(ab, pk(e.x, e.y), a3); i3 = (i3 + k0 + 3) & 127;
            if (q == 0) { e = twm[i4]; a4 = ffma2(ab, pk(e.x, e.y), a4); i4 = (i4 + 4) & 127; }
        }
        int h = chunk*64 + r;
        float cr, ci;
        upk(a0, cr, ci); cr += x0 + (((k0  )&1) ? -x64 : x64); T[h*17 + k0    ] = make_float2(cr, ci);
        upk(a1, cr, ci); cr += x0 + (((k0+1)&1) ? -x64 : x64); T[h*17 + k0 + 1] = make_float2(cr, ci);
        upk(a2, cr, ci); cr += x0 + (((k0+2)&1) ? -x64 : x64); T[h*17 + k0 + 2] = make_float2(cr, ci);
        upk(a3, cr, ci); cr += x0 + (((k0+3)&1) ? -x64 : x64); T[h*17 + k0 + 3] = make_float2(cr, ci);
        if (q == 0) { upk(a4, cr, ci); cr += x0 + x64; T[h*17 + 4] = make_float2(cr, ci); }
        __syncthreads();
    }

    // stage 2: re = P.x + Q.y, im = Q.x - P.y; fold h <-> h+64 by kx parity
    float msum = 0.f;
    if (tid < 136) {
        int kxg = tid / 17, ky = tid % 17;
        int kx0 = kxg*4;
        ull P0=0,Q0=0,P1=0,Q1=0,P2=0,Q2=0,P3=0,Q3=0;
        int i0 = 0, i1 = 0, i2 = 0, i3 = 0;
        for (int h = 0; h < 64; h++) {
            float2 t1 = T[h*17 + ky];
            float2 t2 = T[(h+64)*17 + ky];
            ull SPx = pk(t1.x + t2.x, t1.x + t2.x);
            ull SPy = pk(t1.y + t2.y, t1.y + t2.y);
            ull SMx = pk(t1.x - t2.x, t1.x - t2.x);
            ull SMy = pk(t1.y - t2.y, t1.y - t2.y);
            float2 e;
            e = twp[i0]; i0 = (i0 + kx0    ) & 127; { ull ev = pk(e.x,e.y); P0 = ffma2(SPx, ev, P0); Q0 = ffma2(SPy, ev, Q0); }
            e = twp[i1]; i1 = (i1 + kx0 + 1) & 127; { ull ev = pk(e.x,e.y); P1 = ffma2(SMx, ev, P1); Q1 = ffma2(SMy, ev, Q1); }
            e = twp[i2]; i2 = (i2 + kx0 + 2) & 127; { ull ev = pk(e.x,e.y); P2 = ffma2(SPx, ev, P2); Q2 = ffma2(SPy, ev, Q2); }
            e = twp[i3]; i3 = (i3 + kx0 + 3) & 127; { ull ev = pk(e.x,e.y); P3 = ffma2(SMx, ev, P3); Q3 = ffma2(SMy, ev, Q3); }
        }
        float px, py, qx, qy, a, bb;
        #define FWD_EMIT(Pu, Qu, U) \
            upk(Pu, px, py); upk(Qu, qx, qy); \
            a = (px + qy)*0.0078125f; bb = (qx - py)*0.0078125f; \
            g_lo[bc*MXY + (kx0 + U)*17 + ky] = make_float2(a, bb); \
            msum += sqrtf(a*a + bb*bb);
        FWD_EMIT(P0, Q0, 0)
        FWD_EMIT(P1, Q1, 1)
        FWD_EMIT(P2, Q2, 2)
        FWD_EMIT(P3, Q3, 3)
        #undef FWD_EMIT
    }
    red[tid] = (double)msum; __syncthreads();
    for (int s = 128; s > 0; s >>= 1) {
        if (tid < s) red[tid] += red[tid+s];
        __syncthreads();
    }
    if (tid == 0) g_magpart[bc] = red[0];
}

// per (b,c): filter + spec coefficients, then symmetry-folded inverse DFTs
__global__ void k_coef(const float* __restrict__ wr, const float* __restrict__ wi,
                       const float* __restrict__ mhf_bias,
                       const float* __restrict__ sp_emb,
                       const float* __restrict__ sp_wr, const float* __restrict__ sp_br,
                       const float* __restrict__ sp_wi, const float* __restrict__ sp_bi) {
    int bc = blockIdx.x; int b = bc >> 6, c = bc & 63;
    int hc = c >> 4, oc = c & 15;
    int tid = threadIdx.x;
    __shared__ float2 Fm[MXY], Fs[MXY];
    __shared__ __align__(16) float2 Gm[128*18], Gs[128*18];  // parity-slotted rows
    __shared__ float2 twp[128];
    __shared__ float fes[EDF];
    __shared__ int s_fidx;
    for (int t = tid; t < 128; t += 256) {
        float s, co; sincospif(t * (1.0f/64.0f), &s, &co);
        twp[t] = make_float2(co, s);
    }
    if (tid == 0) {
        double msum = 0.0;
        const double* mp = g_magpart + b*CC;
        for (int i = 0; i < CC; i++) msum += mp[i];
        float mag = (float)(msum / (double)(CC*MXY));
        s_fidx = ((int)(mag * 1000.0f)) % NPF;
    }
    __syncthreads();
    if (tid < EDF) fes[tid] = sp_emb[s_fidx*EDF + tid];
    __syncthreads();

    // phase 1: F coefficients
    const float2* lob = g_lo + b*CC*MXY;
    const float* wrb = wr + (size_t)(hc*CC*OPH + oc)*MXY;
    const float* wib = wi + (size_t)(hc*CC*OPH + oc)*MXY;
    for (int o = tid; o < MXY; o += 256) {
        float mr = 0.f, mi = 0.f;
        for (int i = 0; i < CC; i++) {
            float2 l = lob[i*MXY + o];
            float a = wrb[(size_t)i*OPH*MXY + o];
            float bb = wib[(size_t)i*OPH*MXY + o];
            mr += l.x*a - l.y*bb;
            mi += l.x*bb + l.y*a;
        }
        Fm[o] = make_float2(mr, mi);
        float sr = sp_br[c*MXY + o], si = sp_bi[c*MXY + o];
        for (int e = 0; e < EDF; e++) {
            float f = fes[e];
            sr += f * sp_wr[(size_t)e*(CC*MXY) + c*MXY + o];
            si += f * sp_wi[(size_t)e*(CC*MXY) + c*MXY + o];
        }
        Fs[o] = make_float2(sr, si);
        if (o == 0) {
            g_mhfm[bc]  = mr * 0.0078125f + mhf_bias[c];
            g_specm[bc] = sr * 0.0078125f;
        }
    }
    __syncthreads();

    // stage G folded: h-rep in [0,32] x ky -> 4 h outputs per point.
    for (int o = tid; o < 33*17; o += 256) {
        int h = o/17, ky = o%17;
        ull Pme=0,Qme=0,Pmo=0,Qmo=0, Pse=0,Qse=0,Pso=0,Qso=0;
        int ti = 0;
        #pragma unroll 4
        for (int kx = 0; kx < MX; kx += 2) {
            {
                float2 e = twp[ti]; ti = (ti + h) & 127;
                ull ev = pk(e.x, e.y);
                float2 fm = Fm[kx*17 + ky], fs = Fs[kx*17 + ky];
                Pme = ffma2(pk(fm.x, fm.x), ev, Pme);
                Qme = ffma2(pk(fm.y, fm.y), ev, Qme);
                Pse = ffma2(pk(fs.x, fs.x), ev, Pse);
                Qse = ffma2(pk(fs.y, fs.y), ev, Qse);
            }
            {
                float2 e = twp[ti]; ti = (ti + h) & 127;
                ull ev = pk(e.x, e.y);
                float2 fm = Fm[(kx+1)*17 + ky], fs = Fs[(kx+1)*17 + ky];
                Pmo = ffma2(pk(fm.x, fm.x), ev, Pmo);
                Qmo = ffma2(pk(fm.y, fm.y), ev, Qmo);
                Pso = ffma2(pk(fs.x, fs.x), ev, Pso);
                Qso = ffma2(pk(fs.y, fs.y), ev, Qso);
            }
        }
        int slot = (ky & 1) ? (10 + (ky >> 1)) : (ky >> 1);
        float pex,pey,qex,qey,pox,poy,qox,qoy;
        #define G_EMIT(G, Pe, Qe, Po, Qo) \
            upk(Pe,pex,pey); upk(Qe,qex,qey); upk(Po,pox,poy); upk(Qo,qox,qoy); \
            { float Px=pex+pox, Py=pey+poy, Qx=qex+qox, Qy=qey+qoy; \
              float Mx=pex-pox, My=pey-poy, Nx=qex-qox, Ny=qey-qoy; \
              G[h*18 + slot]        = make_float2(Px - Qy, Py + Qx); \
              G[(h+64)*18 + slot]   = make_float2(Mx - Ny, My + Nx); \
              if (h) { \
                G[(128-h)*18 + slot] = make_float2(Px + Qy, Qx - Py); \
                G[(64-h)*18 + slot]  = make_float2(Mx + Ny, Nx - My); \
              } }
        G_EMIT(Gm, Pme, Qme, Pmo, Qmo)
        G_EMIT(Gs, Pse, Qse, Pso, Qso)
        #undef G_EMIT
    }
    __syncthreads();

    // stage B folded
    float bias = mhf_bias[c];
    const float sc = 0.0078125f;
    float* mout = g_mhf  + (size_t)bc*HW;
    float* sout = g_spec + (size_t)bc*HW;
    {
        int w = tid & 31;
        int hg = tid >> 5;
        ull cse[9], cso[8];
        cse[0] = pk(1.f, 0.f);
        #pragma unroll
        for (int j = 1; j < 9; j++) {
            float2 e = twp[(2*j*w) & 127];
            cse[j] = pk(2.f*e.x, 2.f*e.y);
        }
        #pragma unroll
        for (int j = 0; j < 8; j++) {
            float2 e = twp[((2*j+1)*w) & 127];
            cso[j] = pk(2.f*e.x, 2.f*e.y);
        }
        for (int i = 0; i < 16; i++) {
            int h = hg*16 + i;
            const float4* Ge4m = (const float4*)(Gm + h*18);
            const float4* Go4m = (const float4*)(Gm + h*18 + 10);
            const float4* Ge4s = (const float4*)(Gs + h*18);
            const float4* Go4s = (const float4*)(Gs + h*18 + 10);
            ull me = 0, mo = 0, se = 0, so = 0;
            #pragma unroll
            for (int j2 = 0; j2 < 4; j2++) {
                float4 g = Ge4m[j2];
                me = ffma2(pk(g.x,g.y), cse[2*j2],   me);
                me = ffma2(pk(g.z,g.w), cse[2*j2+1], me);
                float4 s4 = Ge4s[j2];
                se = ffma2(pk(s4.x,s4.y), cse[2*j2],   se);
                se = ffma2(pk(s4.z,s4.w), cse[2*j2+1], se);
            }
            { float2 g = Gm[h*18 + 8]; me = ffma2(pk(g.x,g.y), cse[8], me);
              float2 s2 = Gs[h*18 + 8]; se = ffma2(pk(s2.x,s2.y), cse[8], se); }
            #pragma unroll
            for (int j2 = 0; j2 < 4; j2++) {
                float4 g = Go4m[j2];
                mo = ffma2(pk(g.x,g.y), cso[2*j2],   mo);
                mo = ffma2(pk(g.z,g.w), cso[2*j2+1], mo);
                float4 s4 = Go4s[j2];
                so = ffma2(pk(s4.x,s4.y), cso[2*j2],   so);
                so = ffma2(pk(s4.z,s4.w), cso[2*j2+1], so);
            }
            float Ae,Be,Ao,Bo;
            upk(me,Ae,Be); upk(mo,Ao,Bo);
            {
                float ap=Ae+Ao, bp=Be+Bo, am=Ae-Ao, bm=Be-Bo;
                mout[h*WW + w]        = (ap - bp)*sc + bias;
                mout[h*WW + 64 + w]   = (am - bm)*sc + bias;
                if (w) {
                    mout[h*WW + 128 - w] = (ap + bp)*sc + bias;
                    mout[h*WW + 64 - w]  = (am + bm)*sc + bias;
                }
            }
            upk(se,Ae,Be); upk(so,Ao,Bo);
            {
                float ap=Ae+Ao, bp=Be+Bo, am=Ae-Ao, bm=Be-Bo;
                sout[h*WW + w]        = (ap - bp)*sc;
                sout[h*WW + 64 + w]   = (am - bm)*sc;
                if (w) {
                    sout[h*WW + 128 - w] = (ap + bp)*sc;
                    sout[h*WW + 64 - w]  = (am + bm)*sc;
                }
            }
        }
    }
    // w = 32 orbit {32, 96}
    if (tid < 128) {
        int h = tid;
        ull cse[9], cso[8];
        cse[0] = pk(1.f, 0.f);
        #pragma unroll
        for (int j = 1; j < 9; j++) {
            float2 e = twp[(2*j*32) & 127];
            cse[j] = pk(2.f*e.x, 2.f*e.y);
        }
        #pragma unroll
        for (int j = 0; j < 8; j++) {
            float2 e = twp[((2*j+1)*32) & 127];
            cso[j] = pk(2.f*e.x, 2.f*e.y);
        }
        const float4* Ge4m = (const float4*)(Gm + h*18);
        const float4* Go4m = (const float4*)(Gm + h*18 + 10);
        const float4* Ge4s = (const float4*)(Gs + h*18);
        const float4* Go4s = (const float4*)(Gs + h*18 + 10);
        ull me = 0, mo = 0, se = 0, so = 0;
        #pragma unroll
        for (int j2 = 0; j2 < 4; j2++) {
            float4 g = Ge4m[j2];
            me = ffma2(pk(g.x,g.y), cse[2*j2],   me);
            me = ffma2(pk(g.z,g.w), cse[2*j2+1], me);
            float4 s4 = Ge4s[j2];
            se = ffma2(pk(s4.x,s4.y), cse[2*j2],   se);
            se = ffma2(pk(s4.z,s4.w), cse[2*j2+1], se);
        }
        { float2 g = Gm[h*18 + 8]; me = ffma2(pk(g.x,g.y), cse[8], me);
          float2 s2 = Gs[h*18 + 8]; se = ffma2(pk(s2.x,s2.y), cse[8], se); }
        #pragma unroll
        for (int j2 = 0; j2 < 4; j2++) {
            float4 g = Go4m[j2];
            mo = ffma2(pk(g.x,g.y), cso[2*j2],   mo);
            mo = ffma2(pk(g.z,g.w), cso[2*j2+1], mo);
            float4 s4 = Go4s[j2];
            so = ffma2(pk(s4.x,s4.y), cso[2*j2],   so);
            so = ffma2(pk(s4.z,s4.w), cso[2*j2+1], so);
        }
        float Ae,Be,Ao,Bo;
        upk(me,Ae,Be); upk(mo,Ao,Bo);
        mout[h*WW + 32] = ((Ae+Ao) - (Be+Bo))*sc + bias;
        mout[h*WW + 96] = ((Ae-Ao) - (Be-Bo))*sc + bias;
        upk(se,Ae,Be); upk(so,Ao,Bo);
        sout[h*WW + 32] = ((Ae+Ao) - (Be+Bo))*sc;
        sout[h*WW + 96] = ((Ae-Ao) - (Be-Bo))*sc;
    }
}

__global__ void k_gate(const float* __restrict__ gw1, const float* __restrict__ gb1,
                       const float* __restrict__ gw2, const float* __restrict__ gb2) {
    __shared__ float gi[BB*192];
    __shared__ float h1[BB*64];
    int tid = threadIdx.x;
    // spatial means: reduce 16 partials (fixed order -> deterministic)
    for (int o = tid; o < BB*CC; o += 512) {
        int b = o >> 6, c = o & 63;
        float s = 0.f;
        #pragma unroll
        for (int part = 0; part < SPART; part++)
            s += g_spart[(b*SPART + part)*CC + c];
        gi[b*192 + c] = s * (1.0f/16384.0f);
    }
    for (int o = tid; o < BB*128; o += 512) {
        int b = o >> 7, k = o & 127;
        gi[b*192 + 64 + k] = (k < 64) ? g_mhfm[b*64 + k] : g_specm[b*64 + k - 64];
    }
    __syncthreads();
    {
        int b = tid >> 6, j = tid & 63;
        float a = gb1[j];
        for (int k = 0; k < 192; k++) a += gi[b*192 + k] * gw1[k*64 + j];
        h1[tid] = 0.5f*a*(1.0f + erff(a*0.70710678118654752f));
    }
    __syncthreads();
    if (tid < BB) {
        int b = tid;
        float l[3];
        #pragma unroll
        for (int m = 0; m < 3; m++) {
            float a = gb2[m];
            for (int j = 0; j < 64; j++) a += h1[b*64 + j] * gw2[j*3 + m];
            l[m] = a;
        }
        float mx = fmaxf(l[0], fmaxf(l[1], l[2]));
        float e0 = expf(l[0]-mx), e1 = expf(l[1]-mx), e2 = expf(l[2]-mx);
        float inv = 1.0f/(e0+e1+e2);
        g_gw[b*3+0] = e0*inv; g_gw[b*3+1] = e1*inv; g_gw[b*3+2] = e2*inv;
    }
}

// y = gate-weighted fuse + skip conv + skip_b; accumulate LN stats
__global__ void k_y(const float* __restrict__ x,
                    const float* __restrict__ skip_w,
                    const float* __restrict__ skip_b) {
    int bx = blockIdx.x;
    int b = bx >> 8, tile = bx & 255;
    int pbase = tile * 64;
    int tid = threadIdx.x;
    __shared__ float buf[64*65];
    __shared__ float ys[64*64];
    __shared__ int idxs[64];
    __shared__ float red[256], redq[256];

    if (tid < 64) idxs[tid] = g_idx[b*HW + pbase + tid];
    for (int o = tid; o < 4096; o += 256) {
        int i = o >> 6, p = o & 63;
        buf[i*64 + p] = x[((size_t)(b*64 + i))*HW + pbase + p];
    }
    __syncthreads();
    {
        int pg = tid & 15, cg = tid >> 4;
        ull acc[4][2];
        #pragma unroll
        for (int px = 0; px < 4; px++) { acc[px][0] = 0; acc[px][1] = 0; }
        for (int i = 0; i < 64; i++) {
            float4 xv = *(const float4*)(buf + i*64 + pg*4);
            ull x0 = pk(xv.x, xv.x), x1 = pk(xv.y, xv.y),
                x2 = pk(xv.z, xv.z), x3 = pk(xv.w, xv.w);
            float4 wv = __ldg((const float4*)(skip_w + i*64 + cg*4));
            ull wA = pk(wv.x, wv.y), wB = pk(wv.z, wv.w);
            acc[0][0] = ffma2(x0, wA, acc[0][0]); acc[0][1] = ffma2(x0, wB, acc[0][1]);
            acc[1][0] = ffma2(x1, wA, acc[1][0]); acc[1][1] = ffma2(x1, wB, acc[1][1]);
            acc[2][0] = ffma2(x2, wA, acc[2][0]); acc[2][1] = ffma2(x2, wB, acc[2][1]);
            acc[3][0] = ffma2(x3, wA, acc[3][0]); acc[3][1] = ffma2(x3, wB, acc[3][1]);
        }
        #pragma unroll
        for (int px = 0; px < 4; px++) {
            int p = pg*4 + px;
            #pragma unroll
            for (int u = 0; u < 2; u++) {
                float v0, v1; upk(acc[px][u], v0, v1);
                ys[(cg*4 + 2*u    )*64 + p] = v0;
                ys[(cg*4 + 2*u + 1)*64 + p] = v1;
            }
        }
    }
    __syncthreads();
    for (int o = tid; o < 4096; o += 256) {
        int p = o >> 6, cc2 = o & 63;
        buf[p*65 + cc2] = g_table[idxs[p]*CC + cc2];
    }
    __syncthreads();
    float ga = g_gw[b*3], gbt = g_gw[b*3+1], gm = g_gw[b*3+2];
    float lsum = 0.f, lsq = 0.f;
    for (int o = tid; o < 4096; o += 256) {
        int c = o >> 6, p = o & 63;
        size_t gidx = ((size_t)(b*64 + c))*HW + pbase + p;
        float yv = ga*buf[p*65 + c] + gbt*g_mhf[gidx] + gm*g_spec[gidx]
                 + ys[c*64 + p] + skip_b[c];
        g_y[gidx] = yv;
        lsum += yv; lsq += yv*yv;
    }
    red[tid] = lsum; redq[tid] = lsq; __syncthreads();
    for (int s = 128; s > 0; s >>= 1) {
        if (tid < s) { red[tid] += red[tid+s]; redq[tid] += redq[tid+s]; }
        __syncthreads();
    }
    if (tid == 0) {
        atomicAdd(&g_ysum[b], (double)red[0]);
        atomicAdd(&g_ysq[b],  (double)redq[0]);
    }
}

// layernorm + MLP + residual
__global__ void k_mlp(const float* __restrict__ norm_g, const float* __restrict__ norm_b,
                      const float* __restrict__ w1, const float* __restrict__ b1,
                      const float* __restrict__ w2, const float* __restrict__ b2,
                      float* __restrict__ out) {
    extern __shared__ float sm[];
    float* w12 = sm;               // 8192
    float* yns = sm + 8192;        // 4096
    float* hs  = sm + 8192 + 4096; // 8192
    __shared__ float s_mu, s_rstd;
    int bx = blockIdx.x;
    int b = bx >> 8, tile = bx & 255;
    int pbase = tile * 64;
    int tid = threadIdx.x;

    if (tid == 0) {
        double n = (double)(CC*HW);
        double mu = g_ysum[b] / n;
        double var = g_ysq[b] / n - mu*mu;
        s_mu = (float)mu;
        s_rstd = (float)(1.0 / sqrt(var + 1e-5));
    }
    for (int o = tid; o < 8192; o += 256) w12[o] = w1[o];
    __syncthreads();
    float mu = s_mu, rstd = s_rstd;
    for (int o = tid; o < 4096; o += 256) {
        int c = o >> 6, p = o & 63;
        float yv = g_y[((size_t)(b*64 + c))*HW + pbase + p];
        yns[c*64 + p] = (yv - mu)*rstd*norm_g[c] + norm_b[c];
    }
    __syncthreads();
    {
        int pg = tid & 15, jg = tid >> 4;
        ull acc[4][4];
        #pragma unroll
        for (int px = 0; px < 4; px++)
            #pragma unroll
            for (int u = 0; u < 4; u++) acc[px][u] = 0;
        for (int c = 0; c < 64; c++) {
            float4 yv4 = *(const float4*)(yns + c*64 + pg*4);
            ull y0 = pk(yv4.x, yv4.x), y1 = pk(yv4.y, yv4.y),
                y2 = pk(yv4.z, yv4.z), y3 = pk(yv4.w, yv4.w);
            const float4* wrow = (const float4*)(w12 + c*128 + jg*8);
            float4 wa = wrow[0], wb = wrow[1];
            ull w0 = pk(wa.x, wa.y), w1p = pk(wa.z, wa.w),
                w2p = pk(wb.x, wb.y), w3 = pk(wb.z, wb.w);
            acc[0][0] = ffma2(y0, w0, acc[0][0]); acc[0][1] = ffma2(y0, w1p, acc[0][1]);
            acc[0][2] = ffma2(y0, w2p, acc[0][2]); acc[0][3] = ffma2(y0, w3, acc[0][3]);
            acc[1][0] = ffma2(y1, w0, acc[1][0]); acc[1][1] = ffma2(y1, w1p, acc[1][1]);
            acc[1][2] = ffma2(y1, w2p, acc[1][2]); acc[1][3] = ffma2(y1, w3, acc[1][3]);
            acc[2][0] = ffma2(y2, w0, acc[2][0]); acc[2][1] = ffma2(y2, w1p, acc[2][1]);
            acc[2][2] = ffma2(y2, w2p, acc[2][2]); acc[2][3] = ffma2(y2, w3, acc[2][3]);
            acc[3][0] = ffma2(y3, w0, acc[3][0]); acc[3][1] = ffma2(y3, w1p, acc[3][1]);
            acc[3][2] = ffma2(y3, w2p, acc[3][2]); acc[3][3] = ffma2(y3, w3, acc[3][3]);
        }
        int j0 = jg*8;
        #pragma unroll
        for (int px = 0; px < 4; px++) {
            int p = pg*4 + px;
            #pragma unroll
            for (int u = 0; u < 4; u++) {
                float v0, v1; upk(acc[px][u], v0, v1);
                int j = j0 + 2*u;
                float a0 = v0 + b1[j], a1 = v1 + b1[j+1];
                hs[j*64 + p]     = 0.5f*a0*(1.0f + erff(a0*0.70710678118654752f));
                hs[(j+1)*64 + p] = 0.5f*a1*(1.0f + erff(a1*0.70710678118654752f));
            }
        }
    }
    __syncthreads();
    for (int o = tid; o < 8192; o += 256) w12[o] = w2[o];
    __syncthreads();
    {
        int pg = tid & 15, cg = tid >> 4;
        ull acc2[4][2];
        #pragma unroll
        for (int px = 0; px < 4; px++) { acc2[px][0] = 0; acc2[px][1] = 0; }
        for (int j = 0; j < 128; j++) {
            float4 hv4 = *(const float4*)(hs + j*64 + pg*4);
            ull h0 = pk(hv4.x, hv4.x), h1 = pk(hv4.y, hv4.y),
                h2 = pk(hv4.z, hv4.z), h3 = pk(hv4.w, hv4.w);
            float4 wv = *(const float4*)(w12 + j*64 + cg*4);
            ull wA = pk(wv.x, wv.y), wB = pk(wv.z, wv.w);
            acc2[0][0] = ffma2(h0, wA, acc2[0][0]); acc2[0][1] = ffma2(h0, wB, acc2[0][1]);
            acc2[1][0] = ffma2(h1, wA, acc2[1][0]); acc2[1][1] = ffma2(h1, wB, acc2[1][1]);
            acc2[2][0] = ffma2(h2, wA, acc2[2][0]); acc2[2][1] = ffma2(h2, wB, acc2[2][1]);
            acc2[3][0] = ffma2(h3, wA, acc2[3][0]); acc2[3][1] = ffma2(h3, wB, acc2[3][1]);
        }
        __syncthreads();
        #pragma unroll
        for (int px = 0; px < 4; px++) {
            int p = pg*4 + px;
            #pragma unroll
            for (int u = 0; u < 2; u++) {
                float v0, v1; upk(acc2[px][u], v0, v1);
                yns[(cg*4 + 2*u    )*64 + p] = v0;
                yns[(cg*4 + 2*u + 1)*64 + p] = v1;
            }
        }
    }
    __syncthreads();
    for (int o = tid; o < 4096; o += 256) {
        int c = o >> 6, p = o & 63;
        size_t gi2 = ((size_t)(b*64 + c))*HW + pbase + p;
        out[gi2] = g_y[gi2] + yns[c*64 + p] + b2[c];
    }
}

// ---------------------------------------------------------------------------
extern "C" void kernel_launch(void* const* d_in, const int* in_sizes, int n_in,
                              void* d_out, int out_size) {
    const float* x        = (const float*)d_in[0];
    const float* se_emb   = (const float*)d_in[1];
    const float* se_w     = (const float*)d_in[2];
    const float* se_b     = (const float*)d_in[3];
    const float* mhf_wr   = (const float*)d_in[4];
    const float* mhf_wi   = (const float*)d_in[5];
    const float* mhf_bias = (const float*)d_in[6];
    const float* sp_emb   = (const float*)d_in[7];
    const float* sp_wr    = (const float*)d_in[8];
    const float* sp_br    = (const float*)d_in[9];
    const float* sp_wi    = (const float*)d_in[10];
    const float* sp_bi    = (const float*)d_in[11];
    const float* gate_w1  = (const float*)d_in[12];
    const float* gate_b1  = (const float*)d_in[13];
    const float* gate_w2  = (const float*)d_in[14];
    const float* gate_b2  = (const float*)d_in[15];
    const float* skip_w   = (const float*)d_in[16];
    const float* skip_b   = (const float*)d_in[17];
    const float* norm_g   = (const float*)d_in[18];
    const float* norm_b   = (const float*)d_in[19];
    const float* mlp_w1   = (const float*)d_in[20];
    const float* mlp_b1   = (const float*)d_in[21];
    const float* mlp_w2   = (const float*)d_in[22];
    const float* mlp_b2   = (const float*)d_in[23];
    float* out = (float*)d_out;

    cudaFuncSetAttribute(k_fwd, cudaFuncAttributeMaxDynamicSharedMemorySize, FWD_SMEM);
    cudaFuncSetAttribute(k_mlp, cudaFuncAttributeMaxDynamicSharedMemorySize, MLP_SMEM);

    k_table<<<(NPS*CC + 255)/256, 256>>>(se_emb, se_w, se_b);
    k_hash<<<BB*HH, 128>>>(x);
    k_fwd<<<BB*CC, 256, FWD_SMEM>>>(x);
    k_spat<<<BB*SPART, 256>>>();
    k_coef<<<BB*CC, 256>>>(mhf_wr, mhf_wi, mhf_bias, sp_emb, sp_wr, sp_br, sp_wi, sp_bi);
    k_gate<<<1, 512>>>(gate_w1, gate_b1, gate_w2, gate_b2);
    k_y<<<BB*256, 256>>>(x, skip_w, skip_b);
    k_mlp<<<BB*256, 256, MLP_SMEM>>>(norm_g, norm_b, mlp_w1, mlp_b1, mlp_w2, mlp_b2, out);
}

// round 15
// speedup vs baseline: 1.8322x; 1.0273x over previous
#include <cuda_runtime.h>
#include <math.h>

#define BB 8
#define CC 64
#define HH 128
#define WW 128
#define HW (HH*WW)
#define MX 32
#define MY 17
#define MXY (MX*MY)
#define NPS 10000
#define NPF 5000
#define EDS 64
#define EDF 32
#define NH 4
#define OPH 16
#define SPART 50
#define SPN 200

#define MLP_SMEM ((8192 + 4096 + 8192 + 4096)*4)   /* 98304 B */
#define FWD_SMEM (32768 + 17408 + 1024 + 1024 + 2048)  /* 54272 B */

typedef unsigned long long ull;
__device__ __forceinline__ ull pk(float x, float y){
    ull r; asm("mov.b64 %0, {%1,%2};" : "=l"(r) : "f"(x), "f"(y)); return r;
}
__device__ __forceinline__ void upk(ull v, float& x, float& y){
    asm("mov.b64 {%0,%1}, %2;" : "=f"(x), "=f"(y) : "l"(v));
}
__device__ __forceinline__ ull ffma2(ull a, ull b, ull c){
    ull d; asm("fma.rn.f32x2 %0, %1, %2, %3;" : "=l"(d) : "l"(a), "l"(b), "l"(c)); return d;
}

// ---------------- scratch (static device globals; no runtime alloc) ----------
__device__ float  g_table[NPS*CC];
__device__ int    g_idx[BB*HW];
__device__ int    g_hist[BB*NPS];
__device__ float2 g_lo[BB*CC*MXY];
__device__ double g_magpart[BB*CC];
__device__ float  g_spart[BB*SPART*CC];
__device__ float  g_mhfm[BB*CC];
__device__ float  g_specm[BB*CC];
__device__ float  g_mhf[BB*CC*HW];
__device__ float  g_spec[BB*CC*HW];
__device__ float  g_y[BB*CC*HW];
__device__ double g_ysum[BB];
__device__ double g_ysq[BB];
__device__ float  g_gw[BB*3];

// table[p][c] = sum_e se_emb[p][e]*se_w[e][c] + se_b[c]  (float4, + init fold)
__global__ void k_table(const float* __restrict__ se_emb,
                        const float* __restrict__ se_w,
                        const float* __restrict__ se_b) {
    int t = blockIdx.x*256 + threadIdx.x;     // t < NPS*16
    if (t < BB*NPS) g_hist[t] = 0;
    if (t < BB) { g_ysum[t] = 0.0; g_ysq[t] = 0.0; }
    if (t >= NPS*16) return;
    int cg = t & 15, p = t >> 4;
    float4 acc = *(const float4*)(se_b + cg*4);
    const float* er = se_emb + p*EDS;
    #pragma unroll 8
    for (int e = 0; e < EDS; e++) {
        float ev = er[e];
        float4 wv = __ldg((const float4*)(se_w + e*CC + cg*4));
        acc.x += ev*wv.x; acc.y += ev*wv.y; acc.z += ev*wv.z; acc.w += ev*wv.w;
    }
    *(float4*)(g_table + p*CC + cg*4) = acc;
}

// spatial hash -> idx[b][pix], plus histogram. 4-channel batched staging.
__global__ void k_hash(const float* __restrict__ x) {
    int bid = blockIdx.x;
    int b = bid >> 7, h = bid & 127;
    int w = threadIdx.x;
    int hm = max(h-1, 0), hp = min(h+1, HH-1);
    int wm = max(w-1, 0), wp = min(w+1, WW-1);
    __shared__ int sv[4][128];
    const float* xb = x + (size_t)b*CC*HW;
    float acc = 0.f;
    for (int c = 0; c < CC; c += 4) {
        const float* xc = xb + c*HW;
        int V0 = (int)(xc[hm*WW + w]*100.0f) + (int)(xc[h*WW + w]*100.0f) + (int)(xc[hp*WW + w]*100.0f);
        xc += HW;
        int V1 = (int)(xc[hm*WW + w]*100.0f) + (int)(xc[h*WW + w]*100.0f) + (int)(xc[hp*WW + w]*100.0f);
        xc += HW;
        int V2 = (int)(xc[hm*WW + w]*100.0f) + (int)(xc[h*WW + w]*100.0f) + (int)(xc[hp*WW + w]*100.0f);
        xc += HW;
        int V3 = (int)(xc[hm*WW + w]*100.0f) + (int)(xc[h*WW + w]*100.0f) + (int)(xc[hp*WW + w]*100.0f);
        __syncthreads();   // prior reads of sv complete before overwrite
        sv[0][w] = V0; sv[1][w] = V1; sv[2][w] = V2; sv[3][w] = V3;
        __syncthreads();
        int h0 = sv[0][wm] + sv[0][w] + sv[0][wp];
        int h1 = sv[1][wm] + sv[1][w] + sv[1][wp];
        int h2 = sv[2][wm] + sv[2][w] + sv[2][wp];
        int h3 = sv[3][wm] + sv[3][w] + sv[3][wp];
        acc += (float)(abs(h0) % NPS) + (float)(abs(h1) % NPS)
             + (float)(abs(h2) % NPS) + (float)(abs(h3) % NPS);
    }
    int idx = (int)(acc * 0.015625f);
    g_idx[b*HW + h*WW + w] = idx;
    atomicAdd(&g_hist[b*NPS + idx], 1);
}

// spatial-mean partials: block = (b, part); 50 parts x 200 rows.
__global__ void k_spat() {
    int bp = blockIdx.x;
    int b = bp / SPART, part = bp % SPART;
    int tid = threadIdx.x;           // 128
    int c = tid & 63, rep = tid >> 6;
    int n0 = part*SPN;
    float acc = 0.f;
    const int* hb = g_hist + b*NPS;
    for (int n = n0 + rep; n < n0 + SPN; n += 2) {
        int hv = hb[n];
        if (hv) acc += (float)hv * g_table[n*CC + c];
    }
    __shared__ float red[128];
    red[tid] = acc; __syncthreads();
    if (tid < 64)
        g_spart[(b*SPART + part)*CC + c] = red[c] + red[64 + c];
}

// forward low-mode DFT with w<->128-w folding (stage 1) and
// P/Q + h<->h+64 parity folding (stage 2).
__global__ void k_fwd(const float* __restrict__ x) {
    extern __shared__ float sm[];
    float*  xs  = sm;                        // 64*128 rotated tile chunk
    float2* T   = (float2*)(sm + 8192);      // 128*17
    float2* twp = T + 2176;                  // (cos, sin)
    float2* twm = twp + 128;                 // (cos, -sin)
    double* red = (double*)(twm + 128);      // 256

    int bc = blockIdx.x;
    int tid = threadIdx.x;
    for (int t = tid; t < 128; t += 256) {
        float s, c; sincospif(t * (1.0f/64.0f), &s, &c);
        twp[t] = make_float2(c, s);
        twm[t] = make_float2(c, -s);
    }
    __syncthreads();
    const float* xp = x + (size_t)bc*HW;
    int r = tid & 63, q = tid >> 6;
    int k0 = (q == 0) ? 0 : (4*q + 1);

    for (int chunk = 0; chunk < 2; chunk++) {
        for (int o = tid; o < 8192; o += 256) {
            int rr = o >> 7, w = o & 127;
            xs[rr*128 + ((w + rr) & 127)] = xp[(size_t)(chunk*64 + rr)*WW + w];
        }
        __syncthreads();
        float x0  = xs[r*128 + (r & 127)];
        float x64 = xs[r*128 + ((64 + r) & 127)];
        ull a0 = 0, a1 = 0, a2 = 0, a3 = 0, a4 = 0;
        int i0 = k0, i1 = k0+1, i2 = k0+2, i3 = k0+3, i4 = 4;
        for (int w = 1; w < 64; w++) {
            float v1 = xs[r*128 + ((w + r) & 127)];
            float v2 = xs[r*128 + ((128 - w + r) & 127)];
            ull ab = pk(v1 + v2, v1 - v2);
            float2 e;
            e = twm[i0]; a0 = ffma2(ab, pk(e.x, e.y), a0); i0 = (i0 + k0)     & 127;
            e = twm[i1]; a1 = ffma2(ab, pk(e.x, e.y), a1); i1 = (i1 + k0 + 1) & 127;
            e = twm[i2]; a2 = ffma2(ab, pk(e.x, e.y), a2); i2 = (i2 + k0 + 2) & 127;
            e = twm[i3]; a3 = ffma2(ab, pk(e.x, e.y), a3); i3 = (i3 + k0 + 3) & 127;
            if (q == 0) { e = twm[i4]; a4 = ffma2(ab, pk(e.x, e.y), a4); i4 = (i4 + 4) & 127; }
        }
        int h = chunk*64 + r;
        float cr, ci;
        upk(a0, cr, ci); cr += x0 + (((k0  )&1) ? -x64 : x64); T[h*17 + k0    ] = make_float2(cr, ci);
        upk(a1, cr, ci); cr += x0 + (((k0+1)&1) ? -x64 : x64); T[h*17 + k0 + 1] = make_float2(cr, ci);
        upk(a2, cr, ci); cr += x0 + (((k0+2)&1) ? -x64 : x64); T[h*17 + k0 + 2] = make_float2(cr, ci);
        upk(a3, cr, ci); cr += x0 + (((k0+3)&1) ? -x64 : x64); T[h*17 + k0 + 3] = make_float2(cr, ci);
        if (q == 0) { upk(a4, cr, ci); cr += x0 + x64; T[h*17 + 4] = make_float2(cr, ci); }
        __syncthreads();
    }

    // stage 2: re = P.x + Q.y, im = Q.x - P.y; fold h <-> h+64 by kx parity
    float msum = 0.f;
    if (tid < 136) {
        int kxg = tid / 17, ky = tid % 17;
        int kx0 = kxg*4;
        ull P0=0,Q0=0,P1=0,Q1=0,P2=0,Q2=0,P3=0,Q3=0;
        int i0 = 0, i1 = 0, i2 = 0, i3 = 0;
        for (int h = 0; h < 64; h++) {
            float2 t1 = T[h*17 + ky];
            float2 t2 = T[(h+64)*17 + ky];
            ull SPx = pk(t1.x + t2.x, t1.x + t2.x);
            ull SPy = pk(t1.y + t2.y, t1.y + t2.y);
            ull SMx = pk(t1.x - t2.x, t1.x - t2.x);
            ull SMy = pk(t1.y - t2.y, t1.y - t2.y);
            float2 e;
            e = twp[i0]; i0 = (i0 + kx0    ) & 127; { ull ev = pk(e.x,e.y); P0 = ffma2(SPx, ev, P0); Q0 = ffma2(SPy, ev, Q0); }
            e = twp[i1]; i1 = (i1 + kx0 + 1) & 127; { ull ev = pk(e.x,e.y); P1 = ffma2(SMx, ev, P1); Q1 = ffma2(SMy, ev, Q1); }
            e = twp[i2]; i2 = (i2 + kx0 + 2) & 127; { ull ev = pk(e.x,e.y); P2 = ffma2(SPx, ev, P2); Q2 = ffma2(SPy, ev, Q2); }
            e = twp[i3]; i3 = (i3 + kx0 + 3) & 127; { ull ev = pk(e.x,e.y); P3 = ffma2(SMx, ev, P3); Q3 = ffma2(SMy, ev, Q3); }
        }
        float px, py, qx, qy, a, bb;
        #define FWD_EMIT(Pu, Qu, U) \
            upk(Pu, px, py); upk(Qu, qx, qy); \
            a = (px + qy)*0.0078125f; bb = (qx - py)*0.0078125f; \
            g_lo[bc*MXY + (kx0 + U)*17 + ky] = make_float2(a, bb); \
            msum += sqrtf(a*a + bb*bb);
        FWD_EMIT(P0, Q0, 0)
        FWD_EMIT(P1, Q1, 1)
        FWD_EMIT(P2, Q2, 2)
        FWD_EMIT(P3, Q3, 3)
        #undef FWD_EMIT
    }
    red[tid] = (double)msum; __syncthreads();
    for (int s = 128; s > 0; s >>= 1) {
        if (tid < s) red[tid] += red[tid+s];
        __syncthreads();
    }
    if (tid == 0) g_magpart[bc] = red[0];
}

// per (b,c): filter + spec coefficients, then symmetry-folded inverse DFTs
__global__ void k_coef(const float* __restrict__ wr, const float* __restrict__ wi,
                       const float* __restrict__ mhf_bias,
                       const float* __restrict__ sp_emb,
                       const float* __restrict__ sp_wr, const float* __restrict__ sp_br,
                       const float* __restrict__ sp_wi, const float* __restrict__ sp_bi) {
    int bc = blockIdx.x; int b = bc >> 6, c = bc & 63;
    int hc = c >> 4, oc = c & 15;
    int tid = threadIdx.x;
    __shared__ float2 Fm[MXY], Fs[MXY];
    __shared__ __align__(16) float2 Gm[128*18], Gs[128*18];  // parity-slotted rows
    __shared__ float2 twp[128];
    __shared__ float fes[EDF];
    __shared__ int s_fidx;
    for (int t = tid; t < 128; t += 256) {
        float s, co; sincospif(t * (1.0f/64.0f), &s, &co);
        twp[t] = make_float2(co, s);
    }
    if (tid == 0) {
        double msum = 0.0;
        const double* mp = g_magpart + b*CC;
        for (int i = 0; i < CC; i++) msum += mp[i];
        float mag = (float)(msum / (double)(CC*MXY));
        s_fidx = ((int)(mag * 1000.0f)) % NPF;
    }
    __syncthreads();
    if (tid < EDF) fes[tid] = sp_emb[s_fidx*EDF + tid];
    __syncthreads();

    // phase 1: F coefficients
    const float2* lob = g_lo + b*CC*MXY;
    const float* wrb = wr + (size_t)(hc*CC*OPH + oc)*MXY;
    const float* wib = wi + (size_t)(hc*CC*OPH + oc)*MXY;
    for (int o = tid; o < MXY; o += 256) {
        float mr = 0.f, mi = 0.f;
        for (int i = 0; i < CC; i++) {
            float2 l = lob[i*MXY + o];
            float a = wrb[(size_t)i*OPH*MXY + o];
            float bb = wib[(size_t)i*OPH*MXY + o];
            mr += l.x*a - l.y*bb;
            mi += l.x*bb + l.y*a;
        }
        Fm[o] = make_float2(mr, mi);
        float sr = sp_br[c*MXY + o], si = sp_bi[c*MXY + o];
        for (int e = 0; e < EDF; e++) {
            float f = fes[e];
            sr += f * sp_wr[(size_t)e*(CC*MXY) + c*MXY + o];
            si += f * sp_wi[(size_t)e*(CC*MXY) + c*MXY + o];
        }
        Fs[o] = make_float2(sr, si);
        if (o == 0) {
            g_mhfm[bc]  = mr * 0.0078125f + mhf_bias[c];
            g_specm[bc] = sr * 0.0078125f;
        }
    }
    __syncthreads();

    // stage G folded: h-rep in [0,32] x ky -> 4 h outputs per point.
    for (int o = tid; o < 33*17; o += 256) {
        int h = o/17, ky = o%17;
        ull Pme=0,Qme=0,Pmo=0,Qmo=0, Pse=0,Qse=0,Pso=0,Qso=0;
        int ti = 0;
        #pragma unroll 4
        for (int kx = 0; kx < MX; kx += 2) {
            {
                float2 e = twp[ti]; ti = (ti + h) & 127;
                ull ev = pk(e.x, e.y);
                float2 fm = Fm[kx*17 + ky], fs = Fs[kx*17 + ky];
                Pme = ffma2(pk(fm.x, fm.x), ev, Pme);
                Qme = ffma2(pk(fm.y, fm.y), ev, Qme);
                Pse = ffma2(pk(fs.x, fs.x), ev, Pse);
                Qse = ffma2(pk(fs.y, fs.y), ev, Qse);
            }
            {
                float2 e = twp[ti]; ti = (ti + h) & 127;
                ull ev = pk(e.x, e.y);
                float2 fm = Fm[(kx+1)*17 + ky], fs = Fs[(kx+1)*17 + ky];
                Pmo = ffma2(pk(fm.x, fm.x), ev, Pmo);
                Qmo = ffma2(pk(fm.y, fm.y), ev, Qmo);
                Pso = ffma2(pk(fs.x, fs.x), ev, Pso);
                Qso = ffma2(pk(fs.y, fs.y), ev, Qso);
            }
        }
        int slot = (ky & 1) ? (10 + (ky >> 1)) : (ky >> 1);
        float pex,pey,qex,qey,pox,poy,qox,qoy;
        #define G_EMIT(G, Pe, Qe, Po, Qo) \
            upk(Pe,pex,pey); upk(Qe,qex,qey); upk(Po,pox,poy); upk(Qo,qox,qoy); \
            { float Px=pex+pox, Py=pey+poy, Qx=qex+qox, Qy=qey+qoy; \
              float Mx=pex-pox, My=pey-poy, Nx=qex-qox, Ny=qey-qoy; \
              G[h*18 + slot]        = make_float2(Px - Qy, Py + Qx); \
              G[(h+64)*18 + slot]   = make_float2(Mx - Ny, My + Nx); \
              if (h) { \
                G[(128-h)*18 + slot] = make_float2(Px + Qy, Qx - Py); \
                G[(64-h)*18 + slot]  = make_float2(Mx + Ny, Nx - My); \
              } }
        G_EMIT(Gm, Pme, Qme, Pmo, Qmo)
        G_EMIT(Gs, Pse, Qse, Pso, Qso)
        #undef G_EMIT
    }
    __syncthreads();

    // stage B folded
    float bias = mhf_bias[c];
    const float sc = 0.0078125f;
    float* mout = g_mhf  + (size_t)bc*HW;
    float* sout = g_spec + (size_t)bc*HW;
    {
        int w = tid & 31;
        int hg = tid >> 5;
        ull cse[9], cso[8];
        cse[0] = pk(1.f, 0.f);
        #pragma unroll
        for (int j = 1; j < 9; j++) {
            float2 e = twp[(2*j*w) & 127];
            cse[j] = pk(2.f*e.x, 2.f*e.y);
        }
        #pragma unroll
        for (int j = 0; j < 8; j++) {
            float2 e = twp[((2*j+1)*w) & 127];
            cso[j] = pk(2.f*e.x, 2.f*e.y);
        }
        for (int i = 0; i < 16; i++) {
            int h = hg*16 + i;
            const float4* Ge4m = (const float4*)(Gm + h*18);
            const float4* Go4m = (const float4*)(Gm + h*18 + 10);
            const float4* Ge4s = (const float4*)(Gs + h*18);
            const float4* Go4s = (const float4*)(Gs + h*18 + 10);
            ull me = 0, mo = 0, se = 0, so = 0;
            #pragma unroll
            for (int j2 = 0; j2 < 4; j2++) {
                float4 g = Ge4m[j2];
                me = ffma2(pk(g.x,g.y), cse[2*j2],   me);
                me = ffma2(pk(g.z,g.w), cse[2*j2+1], me);
                float4 s4 = Ge4s[j2];
                se = ffma2(pk(s4.x,s4.y), cse[2*j2],   se);
                se = ffma2(pk(s4.z,s4.w), cse[2*j2+1], se);
            }
            { float2 g = Gm[h*18 + 8]; me = ffma2(pk(g.x,g.y), cse[8], me);
              float2 s2 = Gs[h*18 + 8]; se = ffma2(pk(s2.x,s2.y), cse[8], se); }
            #pragma unroll
            for (int j2 = 0; j2 < 4; j2++) {
                float4 g = Go4m[j2];
                mo = ffma2(pk(g.x,g.y), cso[2*j2],   mo);
                mo = ffma2(pk(g.z,g.w), cso[2*j2+1], mo);
                float4 s4 = Go4s[j2];
                so = ffma2(pk(s4.x,s4.y), cso[2*j2],   so);
                so = ffma2(pk(s4.z,s4.w), cso[2*j2+1], so);
            }
            float Ae,Be,Ao,Bo;
            upk(me,Ae,Be); upk(mo,Ao,Bo);
            {
                float ap=Ae+Ao, bp=Be+Bo, am=Ae-Ao, bm=Be-Bo;
                mout[h*WW + w]        = (ap - bp)*sc + bias;
                mout[h*WW + 64 + w]   = (am - bm)*sc + bias;
                if (w) {
                    mout[h*WW + 128 - w] = (ap + bp)*sc + bias;
                    mout[h*WW + 64 - w]  = (am + bm)*sc + bias;
                }
            }
            upk(se,Ae,Be); upk(so,Ao,Bo);
            {
                float ap=Ae+Ao, bp=Be+Bo, am=Ae-Ao, bm=Be-Bo;
                sout[h*WW + w]        = (ap - bp)*sc;
                sout[h*WW + 64 + w]   = (am - bm)*sc;
                if (w) {
                    sout[h*WW + 128 - w] = (ap + bp)*sc;
                    sout[h*WW + 64 - w]  = (am + bm)*sc;
                }
            }
        }
    }
    // w = 32 orbit {32, 96}
    if (tid < 128) {
        int h = tid;
        ull cse[9], cso[8];
        cse[0] = pk(1.f, 0.f);
        #pragma unroll
        for (int j = 1; j < 9; j++) {
            float2 e = twp[(2*j*32) & 127];
            cse[j] = pk(2.f*e.x, 2.f*e.y);
        }
        #pragma unroll
        for (int j = 0; j < 8; j++) {
            float2 e = twp[((2*j+1)*32) & 127];
            cso[j] = pk(2.f*e.x, 2.f*e.y);
        }
        const float4* Ge4m = (const float4*)(Gm + h*18);
        const float4* Go4m = (const float4*)(Gm + h*18 + 10);
        const float4* Ge4s = (const float4*)(Gs + h*18);
        const float4* Go4s = (const float4*)(Gs + h*18 + 10);
        ull me = 0, mo = 0, se = 0, so = 0;
        #pragma unroll
        for (int j2 = 0; j2 < 4; j2++) {
            float4 g = Ge4m[j2];
            me = ffma2(pk(g.x,g.y), cse[2*j2],   me);
            me = ffma2(pk(g.z,g.w), cse[2*j2+1], me);
            float4 s4 = Ge4s[j2];
            se = ffma2(pk(s4.x,s4.y), cse[2*j2],   se);
            se = ffma2(pk(s4.z,s4.w), cse[2*j2+1], se);
        }
        { float2 g = Gm[h*18 + 8]; me = ffma2(pk(g.x,g.y), cse[8], me);
          float2 s2 = Gs[h*18 + 8]; se = ffma2(pk(s2.x,s2.y), cse[8], se); }
        #pragma unroll
        for (int j2 = 0; j2 < 4; j2++) {
            float4 g = Go4m[j2];
            mo = ffma2(pk(g.x,g.y), cso[2*j2],   mo);
            mo = ffma2(pk(g.z,g.w), cso[2*j2+1], mo);
            float4 s4 = Go4s[j2];
            so = ffma2(pk(s4.x,s4.y), cso[2*j2],   so);
            so = ffma2(pk(s4.z,s4.w), cso[2*j2+1], so);
        }
        float Ae,Be,Ao,Bo;
        upk(me,Ae,Be); upk(mo,Ao,Bo);
        mout[h*WW + 32] = ((Ae+Ao) - (Be+Bo))*sc + bias;
        mout[h*WW + 96] = ((Ae-Ao) - (Be-Bo))*sc + bias;
        upk(se,Ae,Be); upk(so,Ao,Bo);
        sout[h*WW + 32] = ((Ae+Ao) - (Be+Bo))*sc;
        sout[h*WW + 96] = ((Ae-Ao) - (Be-Bo))*sc;
    }
}

__global__ void k_gate(const float* __restrict__ gw1, const float* __restrict__ gb1,
                       const float* __restrict__ gw2, const float* __restrict__ gb2) {
    __shared__ float gi[BB*192];
    __shared__ float h1[BB*64];
    int tid = threadIdx.x;
    // spatial means: reduce 50 partials (fixed order -> deterministic)
    for (int o = tid; o < BB*CC; o += 512) {
        int b = o >> 6, c = o & 63;
        float s = 0.f;
        for (int part = 0; part < SPART; part++)
            s += g_spart[(b*SPART + part)*CC + c];
        gi[b*192 + c] = s * (1.0f/16384.0f);
    }
    for (int o = tid; o < BB*128; o += 512) {
        int b = o >> 7, k = o & 127;
        gi[b*192 + 64 + k] = (k < 64) ? g_mhfm[b*64 + k] : g_specm[b*64 + k - 64];
    }
    __syncthreads();
    {
        int b = tid >> 6, j = tid & 63;
        float a = gb1[j];
        for (int k = 0; k < 192; k++) a += gi[b*192 + k] * gw1[k*64 + j];
        h1[tid] = 0.5f*a*(1.0f + erff(a*0.70710678118654752f));
    }
    __syncthreads();
    if (tid < BB) {
        int b = tid;
        float l[3];
        #pragma unroll
        for (int m = 0; m < 3; m++) {
            float a = gb2[m];
            for (int j = 0; j < 64; j++) a += h1[b*64 + j] * gw2[j*3 + m];
            l[m] = a;
        }
        float mx = fmaxf(l[0], fmaxf(l[1], l[2]));
        float e0 = expf(l[0]-mx), e1 = expf(l[1]-mx), e2 = expf(l[2]-mx);
        float inv = 1.0f/(e0+e1+e2);
        g_gw[b*3+0] = e0*inv; g_gw[b*3+1] = e1*inv; g_gw[b*3+2] = e2*inv;
    }
}

// y = gate-weighted fuse + skip conv + skip_b; accumulate LN stats
__global__ void k_y(const float* __restrict__ x,
                    const float* __restrict__ skip_w,
                    const float* __restrict__ skip_b) {
    int bx = blockIdx.x;
    int b = bx >> 8, tile = bx & 255;
    int pbase = tile * 64;
    int tid = threadIdx.x;
    __shared__ float buf[64*65];
    __shared__ float ys[64*64];
    __shared__ int idxs[64];
    __shared__ float red[256], redq[256];

    if (tid < 64) idxs[tid] = g_idx[b*HW + pbase + tid];
    for (int o = tid; o < 4096; o += 256) {
        int i = o >> 6, p = o & 63;
        buf[i*64 + p] = x[((size_t)(b*64 + i))*HW + pbase + p];
    }
    __syncthreads();
    {
        int pg = tid & 15, cg = tid >> 4;
        ull acc[4][2];
        #pragma unroll
        for (int px = 0; px < 4; px++) { acc[px][0] = 0; acc[px][1] = 0; }
        for (int i = 0; i < 64; i++) {
            float4 xv = *(const float4*)(buf + i*64 + pg*4);
            ull x0 = pk(xv.x, xv.x), x1 = pk(xv.y, xv.y),
                x2 = pk(xv.z, xv.z), x3 = pk(xv.w, xv.w);
            float4 wv = __ldg((const float4*)(skip_w + i*64 + cg*4));
            ull wA = pk(wv.x, wv.y), wB = pk(wv.z, wv.w);
            acc[0][0] = ffma2(x0, wA, acc[0][0]); acc[0][1] = ffma2(x0, wB, acc[0][1]);
            acc[1][0] = ffma2(x1, wA, acc[1][0]); acc[1][1] = ffma2(x1, wB, acc[1][1]);
            acc[2][0] = ffma2(x2, wA, acc[2][0]); acc[2][1] = ffma2(x2, wB, acc[2][1]);
            acc[3][0] = ffma2(x3, wA, acc[3][0]); acc[3][1] = ffma2(x3, wB, acc[3][1]);
        }
        #pragma unroll
        for (int px = 0; px < 4; px++) {
            int p = pg*4 + px;
            #pragma unroll
            for (int u = 0; u < 2; u++) {
                float v0, v1; upk(acc[px][u], v0, v1);
                ys[(cg*4 + 2*u    )*64 + p] = v0;
                ys[(cg*4 + 2*u + 1)*64 + p] = v1;
            }
        }
    }
    __syncthreads();
    for (int o = tid; o < 4096; o += 256) {
        int p = o >> 6, cc2 = o & 63;
        buf[p*65 + cc2] = g_table[idxs[p]*CC + cc2];
    }
    __syncthreads();
    float ga = g_gw[b*3], gbt = g_gw[b*3+1], gm = g_gw[b*3+2];
    float lsum = 0.f, lsq = 0.f;
    for (int o = tid; o < 4096; o += 256) {
        int c = o >> 6, p = o & 63;
        size_t gidx = ((size_t)(b*64 + c))*HW + pbase + p;
        float yv = ga*buf[p*65 + c] + gbt*g_mhf[gidx] + gm*g_spec[gidx]
                 + ys[c*64 + p] + skip_b[c];
        g_y[gidx] = yv;
        lsum += yv; lsq += yv*yv;
    }
    red[tid] = lsum; redq[tid] = lsq; __syncthreads();
    for (int s = 128; s > 0; s >>= 1) {
        if (tid < s) { red[tid] += red[tid+s]; redq[tid] += redq[tid+s]; }
        __syncthreads();
    }
    if (tid == 0) {
        atomicAdd(&g_ysum[b], (double)red[0]);
        atomicAdd(&g_ysq[b],  (double)redq[0]);
    }
}

// layernorm + MLP + residual; y tile staged in smem (read g_y once)
__global__ void k_mlp(const float* __restrict__ norm_g, const float* __restrict__ norm_b,
                      const float* __restrict__ w1, const float* __restrict__ b1,
                      const float* __restrict__ w2, const float* __restrict__ b2,
                      float* __restrict__ out) {
    extern __shared__ float sm[];
    float* w12 = sm;                        // 8192
    float* yns = sm + 8192;                 // 4096
    float* hs  = sm + 8192 + 4096;          // 8192
    float* yt  = sm + 8192 + 4096 + 8192;   // 4096: raw y tile
    __shared__ float s_mu, s_rstd;
    int bx = blockIdx.x;
    int b = bx >> 8, tile = bx & 255;
    int pbase = tile * 64;
    int tid = threadIdx.x;

    if (tid == 0) {
        double n = (double)(CC*HW);
        double mu = g_ysum[b] / n;
        double var = g_ysq[b] / n - mu*mu;
        s_mu = (float)mu;
        s_rstd = (float)(1.0 / sqrt(var + 1e-5));
    }
    for (int o = tid; o < 8192; o += 256) w12[o] = w1[o];
    __syncthreads();
    float mu = s_mu, rstd = s_rstd;
    for (int o = tid; o < 4096; o += 256) {
        int c = o >> 6, p = o & 63;
        float yv = g_y[((size_t)(b*64 + c))*HW + pbase + p];
        yt[c*64 + p] = yv;
        yns[c*64 + p] = (yv - mu)*rstd*norm_g[c] + norm_b[c];
    }
    __syncthreads();
    {
        int pg = tid & 15, jg = tid >> 4;
        ull acc[4][4];
        #pragma unroll
        for (int px = 0; px < 4; px++)
            #pragma unroll
            for (int u = 0; u < 4; u++) acc[px][u] = 0;
        for (int c = 0; c < 64; c++) {
            float4 yv4 = *(const float4*)(yns + c*64 + pg*4);
            ull y0 = pk(yv4.x, yv4.x), y1 = pk(yv4.y, yv4.y),
                y2 = pk(yv4.z, yv4.z), y3 = pk(yv4.w, yv4.w);
            const float4* wrow = (const float4*)(w12 + c*128 + jg*8);
            float4 wa = wrow[0], wb = wrow[1];
            ull w0 = pk(wa.x, wa.y), w1p = pk(wa.z, wa.w),
                w2p = pk(wb.x, wb.y), w3 = pk(wb.z, wb.w);
            acc[0][0] = ffma2(y0, w0, acc[0][0]); acc[0][1] = ffma2(y0, w1p, acc[0][1]);
            acc[0][2] = ffma2(y0, w2p, acc[0][2]); acc[0][3] = ffma2(y0, w3, acc[0][3]);
            acc[1][0] = ffma2(y1, w0, acc[1][0]); acc[1][1] = ffma2(y1, w1p, acc[1][1]);
            acc[1][2] = ffma2(y1, w2p, acc[1][2]); acc[1][3] = ffma2(y1, w3, acc[1][3]);
            acc[2][0] = ffma2(y2, w0, acc[2][0]); acc[2][1] = ffma2(y2, w1p, acc[2][1]);
            acc[2][2] = ffma2(y2, w2p, acc[2][2]); acc[2][3] = ffma2(y2, w3, acc[2][3]);
            acc[3][0] = ffma2(y3, w0, acc[3][0]); acc[3][1] = ffma2(y3, w1p, acc[3][1]);
            acc[3][2] = ffma2(y3, w2p, acc[3][2]); acc[3][3] = ffma2(y3, w3, acc[3][3]);
        }
        int j0 = jg*8;
        #pragma unroll
        for (int px = 0; px < 4; px++) {
            int p = pg*4 + px;
            #pragma unroll
            for (int u = 0; u < 4; u++) {
                float v0, v1; upk(acc[px][u], v0, v1);
                int j = j0 + 2*u;
                float a0 = v0 + b1[j], a1 = v1 + b1[j+1];
                hs[j*64 + p]     = 0.5f*a0*(1.0f + erff(a0*0.70710678118654752f));
                hs[(j+1)*64 + p] = 0.5f*a1*(1.0f + erff(a1*0.70710678118654752f));
            }
        }
    }
    __syncthreads();
    for (int o = tid; o < 8192; o += 256) w12[o] = w2[o];
    __syncthreads();
    {
        int pg = tid & 15, cg = tid >> 4;
        ull acc2[4][2];
        #pragma unroll
        for (int px = 0; px < 4; px++) { acc2[px][0] = 0; acc2[px][1] = 0; }
        for (int j = 0; j < 128; j++) {
            float4 hv4 = *(const float4*)(hs + j*64 + pg*4);
            ull h0 = pk(hv4.x, hv4.x), h1 = pk(hv4.y, hv4.y),
                h2 = pk(hv4.z, hv4.z), h3 = pk(hv4.w, hv4.w);
            float4 wv = *(const float4*)(w12 + j*64 + cg*4);
            ull wA = pk(wv.x, wv.y), wB = pk(wv.z, wv.w);
            acc2[0][0] = ffma2(h0, wA, acc2[0][0]); acc2[0][1] = ffma2(h0, wB, acc2[0][1]);
            acc2[1][0] = ffma2(h1, wA, acc2[1][0]); acc2[1][1] = ffma2(h1, wB, acc2[1][1]);
            acc2[2][0] = ffma2(h2, wA, acc2[2][0]); acc2[2][1] = ffma2(h2, wB, acc2[2][1]);
            acc2[3][0] = ffma2(h3, wA, acc2[3][0]); acc2[3][1] = ffma2(h3, wB, acc2[3][1]);
        }
        __syncthreads();
        #pragma unroll
        for (int px = 0; px < 4; px++) {
            int p = pg*4 + px;
            #pragma unroll
            for (int u = 0; u < 2; u++) {
                float v0, v1; upk(acc2[px][u], v0, v1);
                yns[(cg*4 + 2*u    )*64 + p] = v0;
                yns[(cg*4 + 2*u + 1)*64 + p] = v1;
            }
        }
    }
    __syncthreads();
    for (int o = tid; o < 4096; o += 256) {
        int c = o >> 6, p = o & 63;
        size_t gi2 = ((size_t)(b*64 + c))*HW + pbase + p;
        out[gi2] = yt[c*64 + p] + yns[c*64 + p] + b2[c];
    }
}

// ---------------------------------------------------------------------------
extern "C" void kernel_launch(void* const* d_in, const int* in_sizes, int n_in,
                              void* d_out, int out_size) {
    const float* x        = (const float*)d_in[0];
    const float* se_emb   = (const float*)d_in[1];
    const float* se_w     = (const float*)d_in[2];
    const float* se_b     = (const float*)d_in[3];
    const float* mhf_wr   = (const float*)d_in[4];
    const float* mhf_wi   = (const float*)d_in[5];
    const float* mhf_bias = (const float*)d_in[6];
    const float* sp_emb   = (const float*)d_in[7];
    const float* sp_wr    = (const float*)d_in[8];
    const float* sp_br    = (const float*)d_in[9];
    const float* sp_wi    = (const float*)d_in[10];
    const float* sp_bi    = (const float*)d_in[11];
    const float* gate_w1  = (const float*)d_in[12];
    const float* gate_b1  = (const float*)d_in[13];
    const float* gate_w2  = (const float*)d_in[14];
    const float* gate_b2  = (const float*)d_in[15];
    const float* skip_w   = (const float*)d_in[16];
    const float* skip_b   = (const float*)d_in[17];
    const float* norm_g   = (const float*)d_in[18];
    const float* norm_b   = (const float*)d_in[19];
    const float* mlp_w1   = (const float*)d_in[20];
    const float* mlp_b1   = (const float*)d_in[21];
    const float* mlp_w2   = (const float*)d_in[22];
    const float* mlp_b2   = (const float*)d_in[23];
    float* out = (float*)d_out;

    cudaFuncSetAttribute(k_fwd, cudaFuncAttributeMaxDynamicSharedMemorySize, FWD_SMEM);
    cudaFuncSetAttribute(k_mlp, cudaFuncAttributeMaxDynamicSharedMemorySize, MLP_SMEM);

    k_table<<<(NPS*16 + 255)/256, 256>>>(se_emb, se_w, se_b);
    k_hash<<<BB*HH, 128>>>(x);
    k_fwd<<<BB*CC, 256, FWD_SMEM>>>(x);
    k_spat<<<BB*SPART, 128>>>();
    k_coef<<<BB*CC, 256>>>(mhf_wr, mhf_wi, mhf_bias, sp_emb, sp_wr, sp_br, sp_wi, sp_bi);
    k_gate<<<1, 512>>>(gate_w1, gate_b1, gate_w2, gate_b2);
    k_y<<<BB*256, 256>>>(x, skip_w, skip_b);
    k_mlp<<<BB*256, 256, MLP_SMEM>>>(norm_g, norm_b, mlp_w1, mlp_b1, mlp_w2, mlp_b2, out);
}